// round 3
// baseline (speedup 1.0000x reference)
#include <cuda_runtime.h>
#include <cmath>

// ---------------- problem dims ----------------
#define BATCH   8192
#define D_IN    512
#define D_HID   256
#define D_OUT   128

// gram tiling
#define GTILE   128      // i-tile and j-tile
#define GS      132      // padded smem row stride (floats)
#define NCHUNK  4        // j split into 4 chunks of 2048
#define CHUNKJ  2048

// ---------------- device scratch (no allocations allowed) ----------------
__device__ float g_H[BATCH * D_HID];          // 8 MB
__device__ float g_Y[BATCH * D_OUT];          // 4 MB
__device__ float g_Z[3][BATCH * D_OUT];       // 12 MB
__device__ float g_psum[64][D_OUT];
__device__ float g_psq[64][D_OUT];
__device__ float g_mean[D_OUT];
__device__ float g_sd[D_OUT];
__device__ float g_rspart[5][NCHUNK][BATCH];  // per-gram, per-chunk partial exp-rowsums
__device__ float g_pos[3][BATCH];             // diag of cross grams (BE, BF, EF)

// gram configs: 0:BB 1:EE 2:BE 3:BF 4:EF
__constant__ int c_ga[5]   = {0, 1, 0, 0, 1};
__constant__ int c_gb[5]   = {0, 1, 1, 2, 2};
__constant__ int c_same[5] = {1, 1, 0, 0, 0};
__constant__ int c_pidx[5] = {-1, -1, 0, 1, 2};

// ---------------- packed f32x2 helpers ----------------
__device__ __forceinline__ unsigned long long pack2(float lo, float hi) {
    unsigned long long d;
    asm("mov.b64 %0, {%1, %2};" : "=l"(d) : "f"(lo), "f"(hi));
    return d;
}
__device__ __forceinline__ void unpack2(float& lo, float& hi, unsigned long long v) {
    asm("mov.b64 {%0, %1}, %2;" : "=f"(lo), "=f"(hi) : "l"(v));
}
__device__ __forceinline__ void fma2(unsigned long long& d, unsigned long long a, unsigned long long b) {
    asm("fma.rn.f32x2 %0, %1, %2, %0;" : "+l"(d) : "l"(a), "l"(b));
}

// exp(x) for x in ~[-1.05, 1.05]: degree-8 Taylor, FMA-pipe only. abs err < 1e-5.
__device__ __forceinline__ float fast_exp(float x) {
    float r = 2.48015873e-5f;            // 1/8!
    r = fmaf(r, x, 1.98412698e-4f);      // 1/7!
    r = fmaf(r, x, 1.38888889e-3f);      // 1/6!
    r = fmaf(r, x, 8.33333333e-3f);      // 1/5!
    r = fmaf(r, x, 4.16666667e-2f);      // 1/4!
    r = fmaf(r, x, 1.66666667e-1f);      // 1/3!
    r = fmaf(r, x, 0.5f);
    r = fmaf(r, x, 1.0f);
    r = fmaf(r, x, 1.0f);
    return r;
}

// ---------------- stage 1: MLP GEMMs ----------------
// C[M,N] = act(A[M,K] @ W[K,N] + bias), BM=BN=64, BK=16, 256 thr, 4x4 micro
__global__ __launch_bounds__(256) void mlp_gemm(
    const float* __restrict__ A, const float* __restrict__ W,
    const float* __restrict__ bias, float* __restrict__ C,
    int K, int N, int doRelu)
{
    __shared__ float sA[16][68];   // k-major, padded
    __shared__ float sB[16][64];
    int tid = threadIdx.x;
    int tx = tid & 15, ty = tid >> 4;
    int rowBase = blockIdx.y * 64;
    int colBase = blockIdx.x * 64;

    float c[4][4] = {};

    for (int k0 = 0; k0 < K; k0 += 16) {
        #pragma unroll
        for (int idx = tid; idx < 1024; idx += 256) {
            int r = idx >> 4, kk = idx & 15;
            sA[kk][r] = A[(rowBase + r) * K + k0 + kk];
        }
        #pragma unroll
        for (int idx = tid; idx < 1024; idx += 256) {
            int kk = idx >> 6, n = idx & 63;
            sB[kk][n] = W[(k0 + kk) * N + colBase + n];
        }
        __syncthreads();
        #pragma unroll
        for (int kk = 0; kk < 16; kk++) {
            float a[4], b[4];
            #pragma unroll
            for (int ii = 0; ii < 4; ii++) a[ii] = sA[kk][ty * 4 + ii];
            #pragma unroll
            for (int jj = 0; jj < 4; jj++) b[jj] = sB[kk][tx * 4 + jj];
            #pragma unroll
            for (int ii = 0; ii < 4; ii++)
                #pragma unroll
                for (int jj = 0; jj < 4; jj++)
                    c[ii][jj] = fmaf(a[ii], b[jj], c[ii][jj]);
        }
        __syncthreads();
    }

    #pragma unroll
    for (int ii = 0; ii < 4; ii++) {
        #pragma unroll
        for (int jj = 0; jj < 4; jj++) {
            int col = colBase + tx * 4 + jj;
            float v = c[ii][jj] + bias[col];
            if (doRelu) v = fmaxf(v, 0.0f);
            C[(rowBase + ty * 4 + ii) * N + col] = v;
        }
    }
}

// ---------------- stage 1b: whitening stats ----------------
__global__ void stats_partial() {
    int b = blockIdx.x;       // 64 blocks, 128 rows each
    int t = threadIdx.x;      // column
    float s = 0.0f, q = 0.0f;
    #pragma unroll 8
    for (int r = 0; r < 128; r++) {
        float v = g_Y[(b * 128 + r) * D_OUT + t];
        s += v;
        q = fmaf(v, v, q);
    }
    g_psum[b][t] = s;
    g_psq[b][t] = q;
}

__global__ void stats_final() {
    int t = threadIdx.x;  // 128 threads, one per column
    double s = 0.0, q = 0.0;
    for (int b = 0; b < 64; b++) { s += (double)g_psum[b][t]; q += (double)g_psq[b][t]; }
    double n = (double)BATCH;
    double mean = s / n;
    double var = (q - s * s / n) / (n - 1.0);
    if (var < 0.0) var = 0.0;
    g_mean[t] = (float)mean;
    g_sd[t] = (float)(sqrt(var) + 1e-5);
}

// ---------------- stage 1c: whiten + L2 normalize rows ----------------
__global__ void normalize_rows(int m) {
    __shared__ float warp_ss[4];
    int i = blockIdx.x;
    int t = threadIdx.x;      // 128 threads
    float v = (g_Y[i * D_OUT + t] - g_mean[t]) / g_sd[t];
    float ss = v * v;
    #pragma unroll
    for (int o = 16; o > 0; o >>= 1) ss += __shfl_xor_sync(0xFFFFFFFFu, ss, o);
    if ((t & 31) == 0) warp_ss[t >> 5] = ss;
    __syncthreads();
    float tot = warp_ss[0] + warp_ss[1] + warp_ss[2] + warp_ss[3];
    float nrm = fmaxf(sqrtf(tot), 1e-12f);
    g_Z[m][i * D_OUT + t] = v / nrm;
}

// ---------------- stage 2: gram blocks with fused exp + rowsum ----------------
// grid: (64 i-tiles, 4 j-chunks, 5 grams). block 256 thr, 8x8 micro, f32x2 FMA.
__global__ __launch_bounds__(256, 1) void gram_kernel() {
    extern __shared__ float smem[];
    float* s1 = smem;                 // [128][GS] k-major: s1[k*GS + i]
    float* s2 = smem + GTILE * GS;    // [128][GS] k-major: s2[k*GS + j]

    int tid = threadIdx.x;
    int tx = tid & 15, ty = tid >> 4;
    int g = blockIdx.z;
    const float* __restrict__ Z1 = g_Z[c_ga[g]];
    const float* __restrict__ Z2 = g_Z[c_gb[g]];
    int same = c_same[g];
    int pidx = c_pidx[g];
    int iBase = blockIdx.x * GTILE;
    int chunk = blockIdx.y;

    // load i-tile (once), transposed to k-major. lanes vary k -> coalesced LDG,
    // STS stride GS=132 -> 4-way conflict (load phase only, negligible).
    for (int idx = tid; idx < GTILE * D_OUT; idx += 256) {
        int k = idx & 127, r = idx >> 7;
        s1[k * GS + r] = Z1[(iBase + r) * D_OUT + k];
    }

    const int i0 = ty * 8;
    const int j0 = tx * 8;
    float racc[8] = {0, 0, 0, 0, 0, 0, 0, 0};

    for (int jt = 0; jt < CHUNKJ / GTILE; jt++) {
        int jBase = chunk * CHUNKJ + jt * GTILE;
        __syncthreads();   // also guards s1 on first iter, s2 rewrite later
        for (int idx = tid; idx < GTILE * D_OUT; idx += 256) {
            int k = idx & 127, r = idx >> 7;
            s2[k * GS + r] = Z2[(jBase + r) * D_OUT + k];
        }
        __syncthreads();

        unsigned long long acc[8][4];
        #pragma unroll
        for (int ii = 0; ii < 8; ii++)
            #pragma unroll
            for (int p = 0; p < 4; p++) acc[ii][p] = 0ull;

        #pragma unroll 4
        for (int k = 0; k < D_OUT; k++) {
            const float* ap = s1 + k * GS + i0;
            const float* bp = s2 + k * GS + j0;
            float4 a0 = *(const float4*)(ap);
            float4 a1 = *(const float4*)(ap + 4);
            float4 b0 = *(const float4*)(bp);
            float4 b1 = *(const float4*)(bp + 4);
            unsigned long long bpk[4];
            bpk[0] = pack2(b0.x, b0.y);
            bpk[1] = pack2(b0.z, b0.w);
            bpk[2] = pack2(b1.x, b1.y);
            bpk[3] = pack2(b1.z, b1.w);
            float av[8] = {a0.x, a0.y, a0.z, a0.w, a1.x, a1.y, a1.z, a1.w};
            #pragma unroll
            for (int ii = 0; ii < 8; ii++) {
                unsigned long long apk = pack2(av[ii], av[ii]);
                #pragma unroll
                for (int p = 0; p < 4; p++) fma2(acc[ii][p], apk, bpk[p]);
            }
        }

        // epilogue: exp + rowsum accumulate, diag handling
        #pragma unroll
        for (int ii = 0; ii < 8; ii++) {
            int gi = iBase + i0 + ii;
            float rsum = 0.0f;
            #pragma unroll
            for (int p = 0; p < 4; p++) {
                float x0, x1;
                unpack2(x0, x1, acc[ii][p]);
                int gj0 = jBase + j0 + 2 * p;
                float e0 = fast_exp(x0);
                float e1 = fast_exp(x1);
                if (same) {
                    if (gi == gj0)     e0 = 1.0f;   // masked logit -> exp(0)
                    if (gi == gj0 + 1) e1 = 1.0f;
                } else {
                    if (gi == gj0)     g_pos[pidx][gi] = x0;
                    if (gi == gj0 + 1) g_pos[pidx][gi] = x1;
                }
                rsum += e0 + e1;
            }
            racc[ii] += rsum;
        }
    }

    // deterministic rowsum reduction across tx (16 lanes per row)
    __syncthreads();
    float* red = s2;  // reuse: [128][16]
    #pragma unroll
    for (int ii = 0; ii < 8; ii++) red[(i0 + ii) * 16 + tx] = racc[ii];
    __syncthreads();
    if (tid < 128) {
        float s = 0.0f;
        #pragma unroll
        for (int x = 0; x < 16; x++) s += red[tid * 16 + x];
        g_rspart[g][chunk][iBase + tid] = s;
    }
}

// ---------------- stage 3: final loss ----------------
__global__ void loss_kernel(float* __restrict__ out) {
    __shared__ double sred[256];
    int t = threadIdx.x;
    double acc = 0.0;
    for (int i = t; i < BATCH; i += 256) {
        float rsBB = 0, rsEE = 0, rsBE = 0, rsBF = 0, rsEF = 0;
        #pragma unroll
        for (int c = 0; c < NCHUNK; c++) {
            rsBB += g_rspart[0][c][i];
            rsEE += g_rspart[1][c][i];
            rsBE += g_rspart[2][c][i];
            rsBF += g_rspart[3][c][i];
            rsEF += g_rspart[4][c][i];
        }
        acc += (double)logf(rsBB + rsBE) - (double)g_pos[0][i];
        acc += (double)logf(rsBB + rsBF) - (double)g_pos[1][i];
        acc += (double)logf(rsEE + rsEF) - (double)g_pos[2][i];
    }
    sred[t] = acc;
    __syncthreads();
    for (int s = 128; s > 0; s >>= 1) {
        if (t < s) sred[t] += sred[t + s];
        __syncthreads();
    }
    if (t == 0) out[0] = (float)(sred[0] / (3.0 * (double)BATCH));
}

// ---------------- launch ----------------
extern "C" void kernel_launch(void* const* d_in, const int* in_sizes, int n_in,
                              void* d_out, int out_size)
{
    const float* x[3]  = {(const float*)d_in[0], (const float*)d_in[1], (const float*)d_in[2]};
    const float* W1[3] = {(const float*)d_in[3], (const float*)d_in[7],  (const float*)d_in[11]};
    const float* b1[3] = {(const float*)d_in[4], (const float*)d_in[8],  (const float*)d_in[12]};
    const float* W2[3] = {(const float*)d_in[5], (const float*)d_in[9],  (const float*)d_in[13]};
    const float* b2[3] = {(const float*)d_in[6], (const float*)d_in[10], (const float*)d_in[14]};

    const int gramSmem = 2 * GTILE * GS * sizeof(float);  // 135168 B
    cudaFuncSetAttribute(gram_kernel, cudaFuncAttributeMaxDynamicSharedMemorySize, gramSmem);

    for (int m = 0; m < 3; m++) {
        mlp_gemm<<<dim3(D_HID / 64, BATCH / 64), 256>>>(x[m], W1[m], b1[m], g_H, D_IN, D_HID, 1);
        mlp_gemm<<<dim3(D_OUT / 64, BATCH / 64), 256>>>(g_H, W2[m], b2[m], g_Y, D_HID, D_OUT, 0);
        stats_partial<<<64, 128>>>();
        stats_final<<<1, 128>>>();
        normalize_rows<<<BATCH, 128>>>(m);
    }

    gram_kernel<<<dim3(BATCH / GTILE, NCHUNK, 5), 256, gramSmem>>>();
    loss_kernel<<<1, 256>>>((float*)d_out);
}

// round 6
// speedup vs baseline: 2.7690x; 2.7690x over previous
#include <cuda_runtime.h>
#include <cuda_bf16.h>
#include <cmath>
#include <cstdint>

// ---------------- problem dims ----------------
#define BATCH   8192
#define D_IN    512
#define D_HID   256
#define D_OUT   128

#define GTILE   128
#define NCHUNK  4
#define CHUNKJ  2048

// ---------------- device scratch (no allocations allowed) ----------------
__device__ float g_H[3][BATCH * D_HID];
__device__ float g_Y[3][BATCH * D_OUT];
__device__ __align__(256) __nv_bfloat16 g_Zhi[3][BATCH * D_OUT];
__device__ __align__(256) __nv_bfloat16 g_Zlo[3][BATCH * D_OUT];
__device__ float g_psum[3][64][D_OUT];
__device__ float g_psq[3][64][D_OUT];
__device__ float g_mean[3][D_OUT];
__device__ float g_sd[3][D_OUT];
__device__ float g_rspart[5][NCHUNK][BATCH];
__device__ float g_pos[3][BATCH];

// gram configs: 0:BB 1:EE 2:BE 3:BF 4:EF
__constant__ int c_ga[5]   = {0, 1, 0, 0, 1};
__constant__ int c_gb[5]   = {0, 1, 1, 2, 2};
__constant__ int c_same[5] = {1, 1, 0, 0, 0};
__constant__ int c_pidx[5] = {-1, -1, 0, 1, 2};

// ---------------- PTX helpers (all sm_80-level; no _a features) ----------------
__device__ __forceinline__ uint32_t smem_u32(const void* p) {
    return (uint32_t)__cvta_generic_to_shared(p);
}
__device__ __forceinline__ void cp16(uint32_t dst, const void* src) {
    asm volatile("cp.async.cg.shared.global [%0], [%1], 16;"
                 :: "r"(dst), "l"(__cvta_generic_to_global(src)) : "memory");
}
__device__ __forceinline__ void cp_commit() {
    asm volatile("cp.async.commit_group;" ::: "memory");
}
__device__ __forceinline__ void cp_wait0() {
    asm volatile("cp.async.wait_group 0;" ::: "memory");
}

#define LDSM_X4(r, addr) \
    asm volatile("ldmatrix.sync.aligned.m8n8.x4.shared.b16 {%0,%1,%2,%3}, [%4];" \
        : "=r"((r)[0]), "=r"((r)[1]), "=r"((r)[2]), "=r"((r)[3]) : "r"(addr))

#define MMA16816(d, a, b0, b1) \
    asm volatile("mma.sync.aligned.m16n8k16.row.col.f32.bf16.bf16.f32 " \
        "{%0,%1,%2,%3}, {%4,%5,%6,%7}, {%8,%9}, {%0,%1,%2,%3};" \
        : "+f"((d)[0]), "+f"((d)[1]), "+f"((d)[2]), "+f"((d)[3]) \
        : "r"((a)[0]), "r"((a)[1]), "r"((a)[2]), "r"((a)[3]), "r"(b0), "r"(b1))

// exp(x), |x| <= ~1.05, degree-8 Taylor (FMA pipe only)
__device__ __forceinline__ float fast_exp(float x) {
    float r = 2.48015873e-5f;
    r = fmaf(r, x, 1.98412698e-4f);
    r = fmaf(r, x, 1.38888889e-3f);
    r = fmaf(r, x, 8.33333333e-3f);
    r = fmaf(r, x, 4.16666667e-2f);
    r = fmaf(r, x, 1.66666667e-1f);
    r = fmaf(r, x, 0.5f);
    r = fmaf(r, x, 1.0f);
    r = fmaf(r, x, 1.0f);
    return r;
}

// ---------------- gram smem layout ----------------
// tiles: 128 rows x 128 bf16, row pitch 136 bf16 (272 B) -> conflict-free ldmatrix
#define TPITCH     272
#define TILE_BYTES (128 * TPITCH)          // 34816
#define SOFF_AHI   0
#define SOFF_ALO   TILE_BYTES
#define SOFF_B(buf, which) (2 * TILE_BYTES + (buf) * 2 * TILE_BYTES + (which) * TILE_BYTES)
#define SOFF_RED   (6 * TILE_BYTES)        // float[128][4]
#define GRAM_SMEM  (6 * TILE_BYTES + 2048) // 210944 B

// ---------------- stage 1: MLP GEMMs (3 heads batched on blockIdx.z) ----------------
struct MlpArgs {
    const float* A[3];
    const float* W[3];
    const float* b[3];
    float* C[3];
};

__global__ __launch_bounds__(256) void mlp_gemm(MlpArgs p, int K, int N, int doRelu) {
    __shared__ float sA[16][72];
    __shared__ float sB[16][64];
    int tid = threadIdx.x;
    int tx = tid & 15, ty = tid >> 4;
    int z = blockIdx.z;
    const float* __restrict__ A = p.A[z];
    const float* __restrict__ W = p.W[z];
    const float* __restrict__ bias = p.b[z];
    float* __restrict__ C = p.C[z];
    int rowBase = blockIdx.y * 64;
    int colBase = blockIdx.x * 64;

    float c[4][4] = {};

    for (int k0 = 0; k0 < K; k0 += 16) {
        #pragma unroll
        for (int idx = tid; idx < 1024; idx += 256) {
            int r = idx >> 4, kk = idx & 15;
            sA[kk][r] = A[(rowBase + r) * K + k0 + kk];
        }
        #pragma unroll
        for (int idx = tid; idx < 1024; idx += 256) {
            int kk = idx >> 6, n = idx & 63;
            sB[kk][n] = W[(k0 + kk) * N + colBase + n];
        }
        __syncthreads();
        #pragma unroll
        for (int kk = 0; kk < 16; kk++) {
            float4 a4 = *(const float4*)&sA[kk][ty * 4];
            float4 b4 = *(const float4*)&sB[kk][tx * 4];
            float a[4] = {a4.x, a4.y, a4.z, a4.w};
            float b[4] = {b4.x, b4.y, b4.z, b4.w};
            #pragma unroll
            for (int ii = 0; ii < 4; ii++)
                #pragma unroll
                for (int jj = 0; jj < 4; jj++)
                    c[ii][jj] = fmaf(a[ii], b[jj], c[ii][jj]);
        }
        __syncthreads();
    }

    #pragma unroll
    for (int ii = 0; ii < 4; ii++) {
        #pragma unroll
        for (int jj = 0; jj < 4; jj++) {
            int col = colBase + tx * 4 + jj;
            float v = c[ii][jj] + bias[col];
            if (doRelu) v = fmaxf(v, 0.0f);
            C[(rowBase + ty * 4 + ii) * N + col] = v;
        }
    }
}

// ---------------- stage 1b: whitening stats ----------------
__global__ void stats_partial() {
    int set = blockIdx.y;
    int b = blockIdx.x;
    int t = threadIdx.x;
    float s = 0.0f, q = 0.0f;
    #pragma unroll 8
    for (int r = 0; r < 128; r++) {
        float v = g_Y[set][(b * 128 + r) * D_OUT + t];
        s += v;
        q = fmaf(v, v, q);
    }
    g_psum[set][b][t] = s;
    g_psq[set][b][t] = q;
}

__global__ void stats_final() {
    int set = blockIdx.x;
    int t = threadIdx.x;
    double s = 0.0, q = 0.0;
    for (int b = 0; b < 64; b++) { s += (double)g_psum[set][b][t]; q += (double)g_psq[set][b][t]; }
    double n = (double)BATCH;
    double mean = s / n;
    double var = (q - s * s / n) / (n - 1.0);
    if (var < 0.0) var = 0.0;
    g_mean[set][t] = (float)mean;
    g_sd[set][t] = (float)(sqrt(var) + 1e-5);
}

// ---------------- stage 1c: whiten + L2 normalize + bf16 hi/lo split ----------------
__global__ void normalize_rows() {
    __shared__ float warp_ss[4];
    int set = blockIdx.y;
    int i = blockIdx.x;
    int t = threadIdx.x;
    float v = (g_Y[set][i * D_OUT + t] - g_mean[set][t]) / g_sd[set][t];
    float ss = v * v;
    #pragma unroll
    for (int o = 16; o > 0; o >>= 1) ss += __shfl_xor_sync(0xFFFFFFFFu, ss, o);
    if ((t & 31) == 0) warp_ss[t >> 5] = ss;
    __syncthreads();
    float tot = warp_ss[0] + warp_ss[1] + warp_ss[2] + warp_ss[3];
    float nrm = fmaxf(sqrtf(tot), 1e-12f);
    float z = v / nrm;
    __nv_bfloat16 hi = __float2bfloat16(z);
    g_Zhi[set][i * D_OUT + t] = hi;
    g_Zlo[set][i * D_OUT + t] = __float2bfloat16(z - __bfloat162float(hi));
}

// ---------------- stage 2: mma.sync bf16 gram with fused exp + rowsum ----------------
__device__ __forceinline__ void load_tile_async(uint32_t dstBase, const __nv_bfloat16* src,
                                                int row0, int tid) {
    #pragma unroll
    for (int idx = tid; idx < 2048; idx += 256) {
        int r = idx >> 4, c = idx & 15;
        cp16(dstBase + r * TPITCH + c * 16, src + (row0 + r) * D_OUT + c * 8);
    }
}

__global__ __launch_bounds__(256, 1) void gram_kernel() {
    extern __shared__ unsigned char smem[];
    uint32_t sb = smem_u32(smem);
    float* red = (float*)(smem + SOFF_RED);   // [128][4]

    const int tid = threadIdx.x;
    const int lane = tid & 31;
    const int w = tid >> 5;
    const int wr = w >> 2;                    // 0..1 : 64 rows each
    const int wc = w & 3;                     // 0..3 : 32 cols each
    const int group = lane >> 2;              // 0..7
    const int tig = lane & 3;                 // 0..3

    const int g = blockIdx.z;
    const __nv_bfloat16* __restrict__ Ahi = g_Zhi[c_ga[g]];
    const __nv_bfloat16* __restrict__ Alo = g_Zlo[c_ga[g]];
    const __nv_bfloat16* __restrict__ Bhi = g_Zhi[c_gb[g]];
    const __nv_bfloat16* __restrict__ Blo = g_Zlo[c_gb[g]];
    const int same = c_same[g];
    const int pidx = c_pidx[g];
    const int iBase = blockIdx.x * GTILE;
    const int chunk = blockIdx.y;
    const int jChunk0 = chunk * CHUNKJ;

    // prologue: A hi/lo + first B pair
    load_tile_async(sb + SOFF_AHI, Ahi, iBase, tid);
    load_tile_async(sb + SOFF_ALO, Alo, iBase, tid);
    load_tile_async(sb + SOFF_B(0, 0), Bhi, jChunk0, tid);
    load_tile_async(sb + SOFF_B(0, 1), Blo, jChunk0, tid);
    cp_commit();

    // ldmatrix lane addressing: row = lane&15 (+frag row offset), col half = lane>>4
    const uint32_t rowSel = (uint32_t)(lane & 15) * TPITCH;
    const uint32_t colSel = (uint32_t)((lane >> 4) << 4);
    const uint32_t aHiB = sb + SOFF_AHI + (uint32_t)(wr * 64) * TPITCH + rowSel + colSel;
    const uint32_t aLoB = sb + SOFF_ALO + (uint32_t)(wr * 64) * TPITCH + rowSel + colSel;
    const uint32_t bRowOff = (uint32_t)(wc * 32) * TPITCH + rowSel + colSel;

    float rsacc[8] = {0, 0, 0, 0, 0, 0, 0, 0};

    for (int jt = 0; jt < CHUNKJ / GTILE; jt++) {
        const int buf = jt & 1;
        const int jBase = jChunk0 + jt * GTILE;

        cp_wait0();
        __syncthreads();

        if (jt + 1 < CHUNKJ / GTILE) {
            load_tile_async(sb + SOFF_B(buf ^ 1, 0), Bhi, jBase + GTILE, tid);
            load_tile_async(sb + SOFF_B(buf ^ 1, 1), Blo, jBase + GTILE, tid);
            cp_commit();
        }

        const uint32_t bHiB = sb + SOFF_B(buf, 0) + bRowOff;
        const uint32_t bLoB = sb + SOFF_B(buf, 1) + bRowOff;

        float acc[4][4][4];
        #pragma unroll
        for (int mf = 0; mf < 4; mf++)
            #pragma unroll
            for (int nf = 0; nf < 4; nf++)
                #pragma unroll
                for (int e = 0; e < 4; e++) acc[mf][nf][e] = 0.0f;

        #pragma unroll
        for (int ks = 0; ks < 8; ks++) {
            const uint32_t kb = (uint32_t)ks * 32;
            uint32_t ah[4][4], al[4][4], bh[2][4], bl[2][4];
            #pragma unroll
            for (int mf = 0; mf < 4; mf++) {
                LDSM_X4(ah[mf], aHiB + (uint32_t)(mf * 16) * TPITCH + kb);
                LDSM_X4(al[mf], aLoB + (uint32_t)(mf * 16) * TPITCH + kb);
            }
            #pragma unroll
            for (int ng = 0; ng < 2; ng++) {
                LDSM_X4(bh[ng], bHiB + (uint32_t)(ng * 16) * TPITCH + kb);
                LDSM_X4(bl[ng], bLoB + (uint32_t)(ng * 16) * TPITCH + kb);
            }
            #pragma unroll
            for (int mf = 0; mf < 4; mf++) {
                #pragma unroll
                for (int nf = 0; nf < 4; nf++) {
                    const int ng = nf >> 1, od = nf & 1;
                    MMA16816(acc[mf][nf], ah[mf], bh[ng][od], bh[ng][od + 2]);
                    MMA16816(acc[mf][nf], ah[mf], bl[ng][od], bl[ng][od + 2]);
                    MMA16816(acc[mf][nf], al[mf], bh[ng][od], bh[ng][od + 2]);
                }
            }
        }

        // epilogue: exp + diag + rowsum (rows: wr*64 + mf*16 + group (+8))
        const bool diagTile = (jBase == iBase);
        if (!diagTile) {
            #pragma unroll
            for (int mf = 0; mf < 4; mf++) {
                float s0 = 0.0f, s1 = 0.0f;
                #pragma unroll
                for (int nf = 0; nf < 4; nf++) {
                    s0 += fast_exp(acc[mf][nf][0]) + fast_exp(acc[mf][nf][1]);
                    s1 += fast_exp(acc[mf][nf][2]) + fast_exp(acc[mf][nf][3]);
                }
                rsacc[mf * 2 + 0] += s0;
                rsacc[mf * 2 + 1] += s1;
            }
        } else {
            #pragma unroll
            for (int mf = 0; mf < 4; mf++) {
                const int r0 = wr * 64 + mf * 16 + group;
                float s0 = 0.0f, s1 = 0.0f;
                #pragma unroll
                for (int nf = 0; nf < 4; nf++) {
                    const int c0 = wc * 32 + nf * 8 + tig * 2;
                    #pragma unroll
                    for (int e = 0; e < 4; e++) {
                        const int r = r0 + (e >> 1) * 8;
                        const int c = c0 + (e & 1);
                        float x = acc[mf][nf][e];
                        float ev = fast_exp(x);
                        if (r == c) {
                            if (same) ev = 1.0f;
                            else g_pos[pidx][iBase + r] = x;
                        }
                        if (e < 2) s0 += ev; else s1 += ev;
                    }
                }
                rsacc[mf * 2 + 0] += s0;
                rsacc[mf * 2 + 1] += s1;
            }
        }
    }

    // reduce rowsums: across tig (4 lanes), then across 4 warp-cols via smem
    #pragma unroll
    for (int s = 0; s < 8; s++) {
        float v = rsacc[s];
        v += __shfl_xor_sync(0xFFFFFFFFu, v, 1);
        v += __shfl_xor_sync(0xFFFFFFFFu, v, 2);
        rsacc[s] = v;
    }
    __syncthreads();   // all warps done with smem tiles before reusing RED region
    if (tig == 0) {
        #pragma unroll
        for (int mf = 0; mf < 4; mf++) {
            #pragma unroll
            for (int e = 0; e < 2; e++) {
                int r = wr * 64 + mf * 16 + group + e * 8;
                red[r * 4 + wc] = rsacc[mf * 2 + e];
            }
        }
    }
    __syncthreads();
    if (tid < 128) {
        float s = red[tid * 4 + 0] + red[tid * 4 + 1] + red[tid * 4 + 2] + red[tid * 4 + 3];
        g_rspart[g][chunk][iBase + tid] = s;
    }
}

// ---------------- stage 3: final loss ----------------
__global__ void loss_kernel(float* __restrict__ out) {
    __shared__ double sred[256];
    int t = threadIdx.x;
    double acc = 0.0;
    for (int i = t; i < BATCH; i += 256) {
        float rsBB = 0, rsEE = 0, rsBE = 0, rsBF = 0, rsEF = 0;
        #pragma unroll
        for (int c = 0; c < NCHUNK; c++) {
            rsBB += g_rspart[0][c][i];
            rsEE += g_rspart[1][c][i];
            rsBE += g_rspart[2][c][i];
            rsBF += g_rspart[3][c][i];
            rsEF += g_rspart[4][c][i];
        }
        acc += (double)logf(rsBB + rsBE) - (double)g_pos[0][i];
        acc += (double)logf(rsBB + rsBF) - (double)g_pos[1][i];
        acc += (double)logf(rsEE + rsEF) - (double)g_pos[2][i];
    }
    sred[t] = acc;
    __syncthreads();
    for (int s = 128; s > 0; s >>= 1) {
        if (t < s) sred[t] += sred[t + s];
        __syncthreads();
    }
    if (t == 0) out[0] = (float)(sred[0] / (3.0 * (double)BATCH));
}

// ---------------- launch ----------------
extern "C" void kernel_launch(void* const* d_in, const int* in_sizes, int n_in,
                              void* d_out, int out_size)
{
    const float* x[3]  = {(const float*)d_in[0], (const float*)d_in[1], (const float*)d_in[2]};
    const float* W1[3] = {(const float*)d_in[3], (const float*)d_in[7],  (const float*)d_in[11]};
    const float* b1[3] = {(const float*)d_in[4], (const float*)d_in[8],  (const float*)d_in[12]};
    const float* W2[3] = {(const float*)d_in[5], (const float*)d_in[9],  (const float*)d_in[13]};
    const float* b2[3] = {(const float*)d_in[6], (const float*)d_in[10], (const float*)d_in[14]};

    static float* g_H_ptr = nullptr;
    static float* g_Y_ptr = nullptr;
    if (!g_H_ptr) {
        cudaGetSymbolAddress((void**)&g_H_ptr, g_H);
        cudaGetSymbolAddress((void**)&g_Y_ptr, g_Y);
        cudaFuncSetAttribute(gram_kernel, cudaFuncAttributeMaxDynamicSharedMemorySize, GRAM_SMEM);
    }

    MlpArgs a1, a2;
    for (int m = 0; m < 3; m++) {
        a1.A[m] = x[m];  a1.W[m] = W1[m]; a1.b[m] = b1[m];
        a1.C[m] = g_H_ptr + (size_t)m * BATCH * D_HID;
        a2.A[m] = a1.C[m]; a2.W[m] = W2[m]; a2.b[m] = b2[m];
        a2.C[m] = g_Y_ptr + (size_t)m * BATCH * D_OUT;
    }

    mlp_gemm<<<dim3(D_HID / 64, BATCH / 64, 3), 256>>>(a1, D_IN, D_HID, 1);
    mlp_gemm<<<dim3(D_OUT / 64, BATCH / 64, 3), 256>>>(a2, D_HID, D_OUT, 0);
    stats_partial<<<dim3(64, 3), 128>>>();
    stats_final<<<3, 128>>>();
    normalize_rows<<<dim3(BATCH, 3), 128>>>();

    gram_kernel<<<dim3(BATCH / GTILE, NCHUNK, 5), 256, GRAM_SMEM>>>();
    loss_kernel<<<1, 256>>>((float*)d_out);
}

// round 9
// speedup vs baseline: 4.8892x; 1.7657x over previous
#include <cuda_runtime.h>
#include <cuda_bf16.h>
#include <cmath>
#include <cstdint>

// ---------------- problem dims ----------------
#define BATCH   8192
#define D_IN    512
#define D_HID   256
#define D_OUT   128

#define GTILE   128
#define NCHUNK  4
#define CHUNKJ  2048

// ---------------- device scratch ----------------
__device__ __align__(16) __nv_bfloat16 g_xhi[3][BATCH * D_IN];
__device__ __align__(16) __nv_bfloat16 g_xlo[3][BATCH * D_IN];
__device__ __align__(16) __nv_bfloat16 g_W1t_hi[3][D_HID * D_IN];
__device__ __align__(16) __nv_bfloat16 g_W1t_lo[3][D_HID * D_IN];
__device__ __align__(16) __nv_bfloat16 g_W2t_hi[3][D_OUT * D_HID];
__device__ __align__(16) __nv_bfloat16 g_W2t_lo[3][D_OUT * D_HID];
__device__ __align__(16) __nv_bfloat16 g_Hhi[3][BATCH * D_HID];
__device__ __align__(16) __nv_bfloat16 g_Hlo[3][BATCH * D_HID];
__device__ float g_Y[3][BATCH * D_OUT];
__device__ __align__(16) float g_Zf[3][BATCH * D_OUT];
__device__ __align__(16) __nv_bfloat16 g_Zhi[3][BATCH * D_OUT];
__device__ float g_psum[3][64][D_OUT];
__device__ float g_psq[3][64][D_OUT];
__device__ float g_mean[3][D_OUT];
__device__ float g_sd[3][D_OUT];
__device__ float g_rspart[5][NCHUNK][BATCH];
__device__ float g_pos[3][BATCH];
__device__ double g_lpart[64];

// gram configs: 0:BB 1:EE 2:BE 3:BF 4:EF
__constant__ int c_ga[5]   = {0, 1, 0, 0, 1};
__constant__ int c_gb[5]   = {0, 1, 1, 2, 2};
__constant__ int c_same[5] = {1, 1, 0, 0, 0};

// ---------------- PTX helpers (sm_80-level only) ----------------
__device__ __forceinline__ uint32_t smem_u32(const void* p) {
    return (uint32_t)__cvta_generic_to_shared(p);
}
__device__ __forceinline__ void cp16(uint32_t dst, const void* src) {
    asm volatile("cp.async.cg.shared.global [%0], [%1], 16;"
                 :: "r"(dst), "l"(__cvta_generic_to_global(src)) : "memory");
}
__device__ __forceinline__ void cp_commit() {
    asm volatile("cp.async.commit_group;" ::: "memory");
}
__device__ __forceinline__ void cp_wait0() {
    asm volatile("cp.async.wait_group 0;" ::: "memory");
}

#define LDSM_X4(r, addr) \
    asm volatile("ldmatrix.sync.aligned.m8n8.x4.shared.b16 {%0,%1,%2,%3}, [%4];" \
        : "=r"((r)[0]), "=r"((r)[1]), "=r"((r)[2]), "=r"((r)[3]) : "r"(addr))

#define MMA16816(d, a, b0, b1) \
    asm volatile("mma.sync.aligned.m16n8k16.row.col.f32.bf16.bf16.f32 " \
        "{%0,%1,%2,%3}, {%4,%5,%6,%7}, {%8,%9}, {%0,%1,%2,%3};" \
        : "+f"((d)[0]), "+f"((d)[1]), "+f"((d)[2]), "+f"((d)[3]) \
        : "r"((a)[0]), "r"((a)[1]), "r"((a)[2]), "r"((a)[3]), "r"(b0), "r"(b1))

__device__ __forceinline__ void bsplit(float v, __nv_bfloat16& hi, __nv_bfloat16& lo) {
    hi = __float2bfloat16(v);
    lo = __float2bfloat16(v - __bfloat162float(hi));
}

// ---------------- smem tile geometry ----------------
#define TPITCH     272                      // bytes per 128-col bf16 row (conflict-free ldsm)
#define TILE_BYTES (128 * TPITCH)           // 34816

// generic 128x128 bf16 tile loader (16B chunks), src row stride in elements
__device__ __forceinline__ void load_tile(uint32_t dst, const __nv_bfloat16* src,
                                          int strideElems, int tid) {
    #pragma unroll
    for (int idx = tid; idx < 2048; idx += 256) {
        int r = idx >> 4, c = idx & 15;
        cp16(dst + r * TPITCH + c * 16, src + r * strideElems + c * 8);
    }
}

// one K=128 mma pass: 8 k-steps, 16 m16n8k16 per warp
__device__ __forceinline__ void mma_pass(float acc[4][4][4], uint32_t aBase, uint32_t bBase) {
    #pragma unroll
    for (int ks = 0; ks < 8; ks++) {
        const uint32_t kb = (uint32_t)ks * 32;
        uint32_t a[4][4], b[2][4];
        #pragma unroll
        for (int mf = 0; mf < 4; mf++)
            LDSM_X4(a[mf], aBase + (uint32_t)(mf * 16) * TPITCH + kb);
        #pragma unroll
        for (int ng = 0; ng < 2; ng++)
            LDSM_X4(b[ng], bBase + (uint32_t)(ng * 16) * TPITCH + kb);
        #pragma unroll
        for (int mf = 0; mf < 4; mf++) {
            #pragma unroll
            for (int nf = 0; nf < 4; nf++) {
                const int ng = nf >> 1, od = nf & 1;
                MMA16816(acc[mf][nf], a[mf], b[ng][od], b[ng][od + 2]);
            }
        }
    }
}

// ---------------- stage 0: bf16 hi/lo splits ----------------
__global__ void split_x(const float* xB, const float* xE, const float* xF) {
    int h = blockIdx.y;
    const float* x = (h == 0) ? xB : ((h == 1) ? xE : xF);
    int base = (blockIdx.x * 256 + threadIdx.x) * 4;
    float4 v = *(const float4*)(x + base);
    __nv_bfloat16 h0, h1, h2, h3, l0, l1, l2, l3;
    bsplit(v.x, h0, l0); bsplit(v.y, h1, l1);
    bsplit(v.z, h2, l2); bsplit(v.w, h3, l3);
    __nv_bfloat162* dh = (__nv_bfloat162*)(g_xhi[h] + base);
    __nv_bfloat162* dl = (__nv_bfloat162*)(g_xlo[h] + base);
    dh[0] = __nv_bfloat162(h0, h1); dh[1] = __nv_bfloat162(h2, h3);
    dl[0] = __nv_bfloat162(l0, l1); dl[1] = __nv_bfloat162(l2, l3);
}

struct WArgs { const float* W1[3]; const float* W2[3]; };

__global__ void split_w(WArgs wa) {
    int h = blockIdx.y;
    int idx = blockIdx.x * 256 + threadIdx.x;
    if (idx < D_IN * D_HID) {
        int k = idx >> 8, n = idx & 255;                  // W1 [512][256]
        __nv_bfloat16 hi, lo;
        bsplit(wa.W1[h][idx], hi, lo);
        g_W1t_hi[h][n * D_IN + k] = hi;
        g_W1t_lo[h][n * D_IN + k] = lo;
    } else {
        int i2 = idx - D_IN * D_HID;                      // W2 [256][128]
        int k = i2 >> 7, n = i2 & 127;
        __nv_bfloat16 hi, lo;
        bsplit(wa.W2[h][i2], hi, lo);
        g_W2t_hi[h][n * D_HID + k] = hi;
        g_W2t_lo[h][n * D_HID + k] = lo;
    }
}

// ---------------- stage 1: tensor-core MLP GEMMs ----------------
struct BArgs { const float* b1[3]; const float* b2[3]; };

// H = relu(x @ W1 + b1), written as bf16 hi/lo. grid (64, 2, 3)
__global__ __launch_bounds__(256, 1) void mlp_gemmA(BArgs ba) {
    extern __shared__ unsigned char smem[];
    uint32_t sb = smem_u32(smem);
    const int tid = threadIdx.x, lane = tid & 31, w = tid >> 5;
    const int wr = w >> 2, wc = w & 3, group = lane >> 2, tig = lane & 3;
    const int h = blockIdx.z;
    const int iBase = blockIdx.x * 128, nBase = blockIdx.y * 128;
    const __nv_bfloat16* Xhi = g_xhi[h];
    const __nv_bfloat16* Xlo = g_xlo[h];
    const __nv_bfloat16* Whi = g_W1t_hi[h];
    const __nv_bfloat16* Wlo = g_W1t_lo[h];
    const float* __restrict__ bias = ba.b1[h];

    const uint32_t SA_HI = 0, SA_LO = TILE_BYTES, SB_HI = 2 * TILE_BYTES, SB_LO = 3 * TILE_BYTES;
    const uint32_t rowSel = (uint32_t)(lane & 15) * TPITCH;
    const uint32_t colSel = (uint32_t)((lane >> 4) << 4);
    const uint32_t aOff = (uint32_t)(wr * 64) * TPITCH + rowSel + colSel;
    const uint32_t bOff = (uint32_t)(wc * 32) * TPITCH + rowSel + colSel;

    float acc[4][4][4];
    #pragma unroll
    for (int mf = 0; mf < 4; mf++)
        #pragma unroll
        for (int nf = 0; nf < 4; nf++)
            #pragma unroll
            for (int e = 0; e < 4; e++) acc[mf][nf][e] = 0.0f;

    for (int kc = 0; kc < 4; kc++) {
        const int k0 = kc * 128;
        load_tile(sb + SA_HI, Xhi + (size_t)iBase * D_IN + k0, D_IN, tid);
        load_tile(sb + SA_LO, Xlo + (size_t)iBase * D_IN + k0, D_IN, tid);
        load_tile(sb + SB_HI, Whi + (size_t)nBase * D_IN + k0, D_IN, tid);
        load_tile(sb + SB_LO, Wlo + (size_t)nBase * D_IN + k0, D_IN, tid);
        cp_commit(); cp_wait0();
        __syncthreads();
        mma_pass(acc, sb + SA_HI + aOff, sb + SB_HI + bOff);
        mma_pass(acc, sb + SA_HI + aOff, sb + SB_LO + bOff);
        mma_pass(acc, sb + SA_LO + aOff, sb + SB_HI + bOff);
        __syncthreads();
    }

    #pragma unroll
    for (int mf = 0; mf < 4; mf++) {
        const int r0 = iBase + wr * 64 + mf * 16 + group;
        #pragma unroll
        for (int nf = 0; nf < 4; nf++) {
            const int c0 = nBase + wc * 32 + nf * 8 + tig * 2;
            const float bb0 = bias[c0], bb1 = bias[c0 + 1];
            #pragma unroll
            for (int rr = 0; rr < 2; rr++) {
                const int r = r0 + rr * 8;
                float v0 = fmaxf(acc[mf][nf][rr * 2 + 0] + bb0, 0.0f);
                float v1 = fmaxf(acc[mf][nf][rr * 2 + 1] + bb1, 0.0f);
                __nv_bfloat16 h0, h1, l0, l1;
                bsplit(v0, h0, l0); bsplit(v1, h1, l1);
                *(__nv_bfloat162*)(g_Hhi[h] + (size_t)r * D_HID + c0) = __nv_bfloat162(h0, h1);
                *(__nv_bfloat162*)(g_Hlo[h] + (size_t)r * D_HID + c0) = __nv_bfloat162(l0, l1);
            }
        }
    }
}

// Y = H @ W2 + b2 (fp32 out). grid (64, 1, 3)
__global__ __launch_bounds__(256, 1) void mlp_gemmB(BArgs ba) {
    extern __shared__ unsigned char smem[];
    uint32_t sb = smem_u32(smem);
    const int tid = threadIdx.x, lane = tid & 31, w = tid >> 5;
    const int wr = w >> 2, wc = w & 3, group = lane >> 2, tig = lane & 3;
    const int h = blockIdx.z;
    const int iBase = blockIdx.x * 128;
    const __nv_bfloat16* Ahi = g_Hhi[h];
    const __nv_bfloat16* Alo = g_Hlo[h];
    const __nv_bfloat16* Whi = g_W2t_hi[h];
    const __nv_bfloat16* Wlo = g_W2t_lo[h];
    const float* __restrict__ bias = ba.b2[h];

    const uint32_t SA_HI = 0, SA_LO = TILE_BYTES, SB_HI = 2 * TILE_BYTES, SB_LO = 3 * TILE_BYTES;
    const uint32_t rowSel = (uint32_t)(lane & 15) * TPITCH;
    const uint32_t colSel = (uint32_t)((lane >> 4) << 4);
    const uint32_t aOff = (uint32_t)(wr * 64) * TPITCH + rowSel + colSel;
    const uint32_t bOff = (uint32_t)(wc * 32) * TPITCH + rowSel + colSel;

    float acc[4][4][4];
    #pragma unroll
    for (int mf = 0; mf < 4; mf++)
        #pragma unroll
        for (int nf = 0; nf < 4; nf++)
            #pragma unroll
            for (int e = 0; e < 4; e++) acc[mf][nf][e] = 0.0f;

    for (int kc = 0; kc < 2; kc++) {
        const int k0 = kc * 128;
        load_tile(sb + SA_HI, Ahi + (size_t)iBase * D_HID + k0, D_HID, tid);
        load_tile(sb + SA_LO, Alo + (size_t)iBase * D_HID + k0, D_HID, tid);
        load_tile(sb + SB_HI, Whi + k0, D_HID, tid);
        load_tile(sb + SB_LO, Wlo + k0, D_HID, tid);
        cp_commit(); cp_wait0();
        __syncthreads();
        mma_pass(acc, sb + SA_HI + aOff, sb + SB_HI + bOff);
        mma_pass(acc, sb + SA_HI + aOff, sb + SB_LO + bOff);
        mma_pass(acc, sb + SA_LO + aOff, sb + SB_HI + bOff);
        __syncthreads();
    }

    #pragma unroll
    for (int mf = 0; mf < 4; mf++) {
        const int r0 = iBase + wr * 64 + mf * 16 + group;
        #pragma unroll
        for (int nf = 0; nf < 4; nf++) {
            const int c0 = wc * 32 + nf * 8 + tig * 2;
            const float bb0 = bias[c0], bb1 = bias[c0 + 1];
            #pragma unroll
            for (int rr = 0; rr < 2; rr++) {
                const int r = r0 + rr * 8;
                float2 v;
                v.x = acc[mf][nf][rr * 2 + 0] + bb0;
                v.y = acc[mf][nf][rr * 2 + 1] + bb1;
                *(float2*)(g_Y[h] + (size_t)r * D_OUT + c0) = v;
            }
        }
    }
}

// ---------------- stage 1b: whitening stats ----------------
__global__ void stats_partial() {
    int set = blockIdx.y;
    int b = blockIdx.x;
    int t = threadIdx.x;
    float s = 0.0f, q = 0.0f;
    #pragma unroll 8
    for (int r = 0; r < 128; r++) {
        float v = g_Y[set][(b * 128 + r) * D_OUT + t];
        s += v;
        q = fmaf(v, v, q);
    }
    g_psum[set][b][t] = s;
    g_psq[set][b][t] = q;
}

__global__ void stats_final() {
    int set = blockIdx.x;
    int t = threadIdx.x;
    double s0 = 0.0, s1 = 0.0, q0 = 0.0, q1 = 0.0;
    for (int b = 0; b < 64; b += 2) {
        s0 += (double)g_psum[set][b][t];     q0 += (double)g_psq[set][b][t];
        s1 += (double)g_psum[set][b + 1][t]; q1 += (double)g_psq[set][b + 1][t];
    }
    double s = s0 + s1, q = q0 + q1;
    double n = (double)BATCH;
    double mean = s / n;
    double var = (q - s * s / n) / (n - 1.0);
    if (var < 0.0) var = 0.0;
    g_mean[set][t] = (float)mean;
    g_sd[set][t] = (float)(sqrt(var) + 1e-5);
}

// ---------------- stage 1c: whiten + L2 normalize ----------------
__global__ void normalize_rows() {
    __shared__ float warp_ss[4];
    int set = blockIdx.y;
    int i = blockIdx.x;
    int t = threadIdx.x;
    float v = (g_Y[set][i * D_OUT + t] - g_mean[set][t]) / g_sd[set][t];
    float ss = v * v;
    #pragma unroll
    for (int o = 16; o > 0; o >>= 1) ss += __shfl_xor_sync(0xFFFFFFFFu, ss, o);
    if ((t & 31) == 0) warp_ss[t >> 5] = ss;
    __syncthreads();
    float tot = warp_ss[0] + warp_ss[1] + warp_ss[2] + warp_ss[3];
    float nrm = fmaxf(sqrtf(tot), 1e-12f);
    float z = v / nrm;
    g_Zf[set][i * D_OUT + t] = z;
    g_Zhi[set][i * D_OUT + t] = __float2bfloat16(z);
}

// ---------------- stage 1d: exact fp32 positive logits ----------------
// pairs: 0:(B,E) 1:(B,F) 2:(E,F)
__global__ void pos_kernel() {
    int p = blockIdx.y;
    int a = (p == 2) ? 1 : 0;
    int b = (p == 0) ? 1 : 2;
    int w = threadIdx.x >> 5, lane = threadIdx.x & 31;
    int i = blockIdx.x * 8 + w;
    float4 u = ((const float4*)(g_Zf[a] + (size_t)i * D_OUT))[lane];
    float4 v = ((const float4*)(g_Zf[b] + (size_t)i * D_OUT))[lane];
    float s = u.x * v.x + u.y * v.y + u.z * v.z + u.w * v.w;
    #pragma unroll
    for (int o = 16; o > 0; o >>= 1) s += __shfl_xor_sync(0xFFFFFFFFu, s, o);
    if (lane == 0) g_pos[p][i] = s;
}

// ---------------- stage 2: hi-only bf16 gram with fused exp + rowsum ----------------
#define SOFF_A    0
#define SOFF_B(b) (TILE_BYTES + (b) * TILE_BYTES)
#define SOFF_RED  (3 * TILE_BYTES)
#define GRAM_SMEM (3 * TILE_BYTES + 2048)   // 106496

__global__ __launch_bounds__(256, 2) void gram_kernel() {
    extern __shared__ unsigned char smem[];
    uint32_t sb = smem_u32(smem);
    float* red = (float*)(smem + SOFF_RED);

    const int tid = threadIdx.x, lane = tid & 31, w = tid >> 5;
    const int wr = w >> 2, wc = w & 3, group = lane >> 2, tig = lane & 3;

    const int g = blockIdx.z;
    const __nv_bfloat16* __restrict__ A = g_Zhi[c_ga[g]];
    const __nv_bfloat16* __restrict__ B = g_Zhi[c_gb[g]];
    const int same = c_same[g];
    const int iBase = blockIdx.x * GTILE;
    const int chunk = blockIdx.y;
    const int jChunk0 = chunk * CHUNKJ;

    load_tile(sb + SOFF_A, A + (size_t)iBase * D_OUT, D_OUT, tid);
    load_tile(sb + SOFF_B(0), B + (size_t)jChunk0 * D_OUT, D_OUT, tid);
    cp_commit();

    const uint32_t rowSel = (uint32_t)(lane & 15) * TPITCH;
    const uint32_t colSel = (uint32_t)((lane >> 4) << 4);
    const uint32_t aBase = sb + SOFF_A + (uint32_t)(wr * 64) * TPITCH + rowSel + colSel;
    const uint32_t bOff = (uint32_t)(wc * 32) * TPITCH + rowSel + colSel;

    float rsacc[8] = {0, 0, 0, 0, 0, 0, 0, 0};

    for (int jt = 0; jt < CHUNKJ / GTILE; jt++) {
        const int buf = jt & 1;
        const int jBase = jChunk0 + jt * GTILE;

        cp_wait0();
        __syncthreads();

        if (jt + 1 < CHUNKJ / GTILE) {
            load_tile(sb + SOFF_B(buf ^ 1), B + (size_t)(jBase + GTILE) * D_OUT, D_OUT, tid);
            cp_commit();
        }

        const uint32_t bBase = sb + SOFF_B(buf) + bOff;

        float acc[4][4][4];
        #pragma unroll
        for (int mf = 0; mf < 4; mf++)
            #pragma unroll
            for (int nf = 0; nf < 4; nf++)
                #pragma unroll
                for (int e = 0; e < 4; e++) acc[mf][nf][e] = 0.0f;

        mma_pass(acc, aBase, bBase);

        // epilogue: exp + rowsum; masked diag only on same-gram diagonal tiles
        if (!(same && jBase == iBase)) {
            #pragma unroll
            for (int mf = 0; mf < 4; mf++) {
                float s0 = 0.0f, s1 = 0.0f;
                #pragma unroll
                for (int nf = 0; nf < 4; nf++) {
                    s0 += __expf(acc[mf][nf][0]) + __expf(acc[mf][nf][1]);
                    s1 += __expf(acc[mf][nf][2]) + __expf(acc[mf][nf][3]);
                }
                rsacc[mf * 2 + 0] += s0;
                rsacc[mf * 2 + 1] += s1;
            }
        } else {
            #pragma unroll
            for (int mf = 0; mf < 4; mf++) {
                const int r0 = wr * 64 + mf * 16 + group;
                float s0 = 0.0f, s1 = 0.0f;
                #pragma unroll
                for (int nf = 0; nf < 4; nf++) {
                    const int c0 = wc * 32 + nf * 8 + tig * 2;
                    #pragma unroll
                    for (int e = 0; e < 4; e++) {
                        const int r = r0 + (e >> 1) * 8;
                        const int c = c0 + (e & 1);
                        float ev = (r == c) ? 1.0f : __expf(acc[mf][nf][e]);
                        if (e < 2) s0 += ev; else s1 += ev;
                    }
                }
                rsacc[mf * 2 + 0] += s0;
                rsacc[mf * 2 + 1] += s1;
            }
        }
    }

    #pragma unroll
    for (int s = 0; s < 8; s++) {
        float v = rsacc[s];
        v += __shfl_xor_sync(0xFFFFFFFFu, v, 1);
        v += __shfl_xor_sync(0xFFFFFFFFu, v, 2);
        rsacc[s] = v;
    }
    __syncthreads();
    if (tig == 0) {
        #pragma unroll
        for (int mf = 0; mf < 4; mf++) {
            #pragma unroll
            for (int e = 0; e < 2; e++) {
                int r = wr * 64 + mf * 16 + group + e * 8;
                red[r * 4 + wc] = rsacc[mf * 2 + e];
            }
        }
    }
    __syncthreads();
    if (tid < 128) {
        float s = red[tid * 4 + 0] + red[tid * 4 + 1] + red[tid * 4 + 2] + red[tid * 4 + 3];
        g_rspart[g][chunk][iBase + tid] = s;
    }
}

// ---------------- stage 3: loss (two-stage, deterministic) ----------------
__global__ void loss_part() {
    __shared__ double sred[128];
    int t = threadIdx.x;
    int i = blockIdx.x * 128 + t;
    float rsBB = 0, rsEE = 0, rsBE = 0, rsBF = 0, rsEF = 0;
    #pragma unroll
    for (int c = 0; c < NCHUNK; c++) {
        rsBB += g_rspart[0][c][i];
        rsEE += g_rspart[1][c][i];
        rsBE += g_rspart[2][c][i];
        rsBF += g_rspart[3][c][i];
        rsEF += g_rspart[4][c][i];
    }
    double acc = 0.0;
    acc += (double)logf(rsBB + rsBE) - (double)g_pos[0][i];
    acc += (double)logf(rsBB + rsBF) - (double)g_pos[1][i];
    acc += (double)logf(rsEE + rsEF) - (double)g_pos[2][i];
    sred[t] = acc;
    __syncthreads();
    for (int s = 64; s > 0; s >>= 1) {
        if (t < s) sred[t] += sred[t + s];
        __syncthreads();
    }
    if (t == 0) g_lpart[blockIdx.x] = sred[0];
}

__global__ void loss_final(float* __restrict__ out) {
    __shared__ double s[64];
    int t = threadIdx.x;
    s[t] = g_lpart[t];
    __syncthreads();
    for (int k = 32; k > 0; k >>= 1) {
        if (t < k) s[t] += s[t + k];
        __syncthreads();
    }
    if (t == 0) out[0] = (float)(s[0] / (3.0 * (double)BATCH));
}

// ---------------- launch ----------------
extern "C" void kernel_launch(void* const* d_in, const int* in_sizes, int n_in,
                              void* d_out, int out_size)
{
    static bool inited = false;
    if (!inited) {
        cudaFuncSetAttribute(gram_kernel, cudaFuncAttributeMaxDynamicSharedMemorySize, GRAM_SMEM);
        cudaFuncSetAttribute(mlp_gemmA, cudaFuncAttributeMaxDynamicSharedMemorySize, 4 * TILE_BYTES);
        cudaFuncSetAttribute(mlp_gemmB, cudaFuncAttributeMaxDynamicSharedMemorySize, 4 * TILE_BYTES);
        inited = true;
    }

    WArgs wa;
    BArgs ba;
    for (int m = 0; m < 3; m++) {
        wa.W1[m] = (const float*)d_in[3 + 4 * m];
        ba.b1[m] = (const float*)d_in[4 + 4 * m];
        wa.W2[m] = (const float*)d_in[5 + 4 * m];
        ba.b2[m] = (const float*)d_in[6 + 4 * m];
    }

    split_x<<<dim3(BATCH * D_IN / 1024, 3), 256>>>(
        (const float*)d_in[0], (const float*)d_in[1], (const float*)d_in[2]);
    split_w<<<dim3((D_IN * D_HID + D_HID * D_OUT) / 256, 3), 256>>>(wa);

    mlp_gemmA<<<dim3(BATCH / 128, 2, 3), 256, 4 * TILE_BYTES>>>(ba);
    mlp_gemmB<<<dim3(BATCH / 128, 1, 3), 256, 4 * TILE_BYTES>>>(ba);

    stats_partial<<<dim3(64, 3), 128>>>();
    stats_final<<<3, 128>>>();
    normalize_rows<<<dim3(BATCH, 3), 128>>>();
    pos_kernel<<<dim3(BATCH / 8, 3), 256>>>();

    gram_kernel<<<dim3(BATCH / GTILE, NCHUNK, 5), 256, GRAM_SMEM>>>();

    loss_part<<<64, 128>>>();
    loss_final<<<1, 64>>>((float*)d_out);
}

// round 10
// speedup vs baseline: 7.5719x; 1.5487x over previous
#include <cuda_runtime.h>
#include <cuda_bf16.h>
#include <cmath>
#include <cstdint>

// ---------------- problem dims ----------------
#define BATCH   8192
#define D_IN    512
#define D_HID   256
#define D_OUT   128

#define GTILE   128
#define NCHUNK  4
#define CHUNKJ  2048

// sqrt(log2(e)): Zhi scaled by this => gram accumulators are log2-domain
#define ZSCALE  1.2011224087864498f
#define LN2F    0.6931471805599453f

// ---------------- device scratch ----------------
__device__ __align__(16) __nv_bfloat16 g_xhi[3][BATCH * D_IN];
__device__ __align__(16) __nv_bfloat16 g_xlo[3][BATCH * D_IN];
__device__ __align__(16) __nv_bfloat16 g_W1t_hi[3][D_HID * D_IN];
__device__ __align__(16) __nv_bfloat16 g_W1t_lo[3][D_HID * D_IN];
__device__ __align__(16) __nv_bfloat16 g_W2t_hi[3][D_OUT * D_HID];
__device__ __align__(16) __nv_bfloat16 g_W2t_lo[3][D_OUT * D_HID];
__device__ __align__(16) __nv_bfloat16 g_Hhi[3][BATCH * D_HID];
__device__ __align__(16) __nv_bfloat16 g_Hlo[3][BATCH * D_HID];
__device__ float g_Y[3][BATCH * D_OUT];
__device__ __align__(16) __nv_bfloat16 g_Zhi[3][BATCH * D_OUT];
__device__ float g_psum[3][64][D_OUT];
__device__ float g_psq[3][64][D_OUT];
__device__ float g_mean[3][D_OUT];
__device__ float g_sd[3][D_OUT];
__device__ float g_rspart[5][NCHUNK][BATCH];
__device__ float g_pos[3][BATCH];
__device__ double g_lpart[64];

// gram configs: 0:BB 1:EE 2:BE 3:BF 4:EF
__constant__ int c_ga[5]   = {0, 1, 0, 0, 1};
__constant__ int c_gb[5]   = {0, 1, 1, 2, 2};
__constant__ int c_same[5] = {1, 1, 0, 0, 0};

// ---------------- PTX helpers (sm_80-level only) ----------------
__device__ __forceinline__ uint32_t smem_u32(const void* p) {
    return (uint32_t)__cvta_generic_to_shared(p);
}
__device__ __forceinline__ void cp16(uint32_t dst, const void* src) {
    asm volatile("cp.async.cg.shared.global [%0], [%1], 16;"
                 :: "r"(dst), "l"(__cvta_generic_to_global(src)) : "memory");
}
__device__ __forceinline__ void cp_commit() {
    asm volatile("cp.async.commit_group;" ::: "memory");
}
__device__ __forceinline__ void cp_wait0() {
    asm volatile("cp.async.wait_group 0;" ::: "memory");
}

#define LDSM_X4(r, addr) \
    asm volatile("ldmatrix.sync.aligned.m8n8.x4.shared.b16 {%0,%1,%2,%3}, [%4];" \
        : "=r"((r)[0]), "=r"((r)[1]), "=r"((r)[2]), "=r"((r)[3]) : "r"(addr))

#define MMA16816(d, a, b0, b1) \
    asm volatile("mma.sync.aligned.m16n8k16.row.col.f32.bf16.bf16.f32 " \
        "{%0,%1,%2,%3}, {%4,%5,%6,%7}, {%8,%9}, {%0,%1,%2,%3};" \
        : "+f"((d)[0]), "+f"((d)[1]), "+f"((d)[2]), "+f"((d)[3]) \
        : "r"((a)[0]), "r"((a)[1]), "r"((a)[2]), "r"((a)[3]), "r"(b0), "r"(b1))

__device__ __forceinline__ void bsplit(float v, __nv_bfloat16& hi, __nv_bfloat16& lo) {
    hi = __float2bfloat16(v);
    lo = __float2bfloat16(v - __bfloat162float(hi));
}

// MUFU 2^x
__device__ __forceinline__ float ex2(float x) {
    float y;
    asm("ex2.approx.f32 %0, %1;" : "=f"(y) : "f"(x));
    return y;
}
// FMA-pipe 2^x via e^(x ln2), |x| <= ~1.52 -> |t| <= 1.06
__device__ __forceinline__ float tex2(float x) {
    float t = x * LN2F;
    float r = 2.48015873e-5f;
    r = fmaf(r, t, 1.98412698e-4f);
    r = fmaf(r, t, 1.38888889e-3f);
    r = fmaf(r, t, 8.33333333e-3f);
    r = fmaf(r, t, 4.16666667e-2f);
    r = fmaf(r, t, 1.66666667e-1f);
    r = fmaf(r, t, 0.5f);
    r = fmaf(r, t, 1.0f);
    r = fmaf(r, t, 1.0f);
    return r;
}

// ---------------- smem tile geometry ----------------
// 128x128 bf16 tile, 272B pitch (gram)
#define TPITCH     272
#define TILE_BYTES (128 * TPITCH)           // 34816
// 128x64 bf16 tile, 144B pitch (MLP k-chunks)
#define TP64       144
#define T64B       (128 * TP64)             // 18432

__device__ __forceinline__ void load_tile(uint32_t dst, const __nv_bfloat16* src,
                                          int strideElems, int tid) {
    #pragma unroll
    for (int idx = tid; idx < 2048; idx += 256) {
        int r = idx >> 4, c = idx & 15;
        cp16(dst + r * TPITCH + c * 16, src + r * strideElems + c * 8);
    }
}
__device__ __forceinline__ void load_tile64(uint32_t dst, const __nv_bfloat16* src,
                                            int strideElems, int tid) {
    #pragma unroll
    for (int idx = tid; idx < 1024; idx += 256) {
        int r = idx >> 3, c = idx & 7;
        cp16(dst + r * TP64 + c * 16, src + r * strideElems + c * 8);
    }
}

// K=128 mma pass (gram)
__device__ __forceinline__ void mma_pass(float acc[4][4][4], uint32_t aBase, uint32_t bBase) {
    #pragma unroll
    for (int ks = 0; ks < 8; ks++) {
        const uint32_t kb = (uint32_t)ks * 32;
        uint32_t a[4][4], b[2][4];
        #pragma unroll
        for (int mf = 0; mf < 4; mf++)
            LDSM_X4(a[mf], aBase + (uint32_t)(mf * 16) * TPITCH + kb);
        #pragma unroll
        for (int ng = 0; ng < 2; ng++)
            LDSM_X4(b[ng], bBase + (uint32_t)(ng * 16) * TPITCH + kb);
        #pragma unroll
        for (int mf = 0; mf < 4; mf++) {
            #pragma unroll
            for (int nf = 0; nf < 4; nf++) {
                const int ng = nf >> 1, od = nf & 1;
                MMA16816(acc[mf][nf], a[mf], b[ng][od], b[ng][od + 2]);
            }
        }
    }
}
// K=64 mma pass (MLP)
__device__ __forceinline__ void mma_pass64(float acc[4][4][4], uint32_t aBase, uint32_t bBase) {
    #pragma unroll
    for (int ks = 0; ks < 4; ks++) {
        const uint32_t kb = (uint32_t)ks * 32;
        uint32_t a[4][4], b[2][4];
        #pragma unroll
        for (int mf = 0; mf < 4; mf++)
            LDSM_X4(a[mf], aBase + (uint32_t)(mf * 16) * TP64 + kb);
        #pragma unroll
        for (int ng = 0; ng < 2; ng++)
            LDSM_X4(b[ng], bBase + (uint32_t)(ng * 16) * TP64 + kb);
        #pragma unroll
        for (int mf = 0; mf < 4; mf++) {
            #pragma unroll
            for (int nf = 0; nf < 4; nf++) {
                const int ng = nf >> 1, od = nf & 1;
                MMA16816(acc[mf][nf], a[mf], b[ng][od], b[ng][od + 2]);
            }
        }
    }
}

// ---------------- stage 0: bf16 hi/lo splits ----------------
__global__ void split_x(const float* xB, const float* xE, const float* xF) {
    int h = blockIdx.y;
    const float* x = (h == 0) ? xB : ((h == 1) ? xE : xF);
    int base = (blockIdx.x * 256 + threadIdx.x) * 4;
    float4 v = *(const float4*)(x + base);
    __nv_bfloat16 h0, h1, h2, h3, l0, l1, l2, l3;
    bsplit(v.x, h0, l0); bsplit(v.y, h1, l1);
    bsplit(v.z, h2, l2); bsplit(v.w, h3, l3);
    __nv_bfloat162* dh = (__nv_bfloat162*)(g_xhi[h] + base);
    __nv_bfloat162* dl = (__nv_bfloat162*)(g_xlo[h] + base);
    dh[0] = __nv_bfloat162(h0, h1); dh[1] = __nv_bfloat162(h2, h3);
    dl[0] = __nv_bfloat162(l0, l1); dl[1] = __nv_bfloat162(l2, l3);
}

struct WArgs { const float* W1[3]; const float* W2[3]; };

__global__ void split_w(WArgs wa) {
    int h = blockIdx.y;
    int idx = blockIdx.x * 256 + threadIdx.x;
    if (idx < D_IN * D_HID) {
        int k = idx >> 8, n = idx & 255;
        __nv_bfloat16 hi, lo;
        bsplit(wa.W1[h][idx], hi, lo);
        g_W1t_hi[h][n * D_IN + k] = hi;
        g_W1t_lo[h][n * D_IN + k] = lo;
    } else {
        int i2 = idx - D_IN * D_HID;
        int k = i2 >> 7, n = i2 & 127;
        __nv_bfloat16 hi, lo;
        bsplit(wa.W2[h][i2], hi, lo);
        g_W2t_hi[h][n * D_HID + k] = hi;
        g_W2t_lo[h][n * D_HID + k] = lo;
    }
}

// ---------------- stage 1: tensor-core MLP GEMMs (double-buffered k64 chunks) ----------------
struct BArgs { const float* b1[3]; const float* b2[3]; };

#define MBUF(buf, which) ((uint32_t)(((buf) * 4 + (which)) * T64B))
#define MLP_SMEM (8 * T64B)   // 147456

// H = relu(x @ W1 + b1) -> bf16 hi/lo. grid (64, 2, 3)
__global__ __launch_bounds__(256, 1) void mlp_gemmA(BArgs ba) {
    extern __shared__ unsigned char smem[];
    uint32_t sb = smem_u32(smem);
    const int tid = threadIdx.x, lane = tid & 31, w = tid >> 5;
    const int wr = w >> 2, wc = w & 3, group = lane >> 2, tig = lane & 3;
    const int h = blockIdx.z;
    const int iBase = blockIdx.x * 128, nBase = blockIdx.y * 128;
    const __nv_bfloat16* Xhi = g_xhi[h];
    const __nv_bfloat16* Xlo = g_xlo[h];
    const __nv_bfloat16* Whi = g_W1t_hi[h];
    const __nv_bfloat16* Wlo = g_W1t_lo[h];
    const float* __restrict__ bias = ba.b1[h];

    const uint32_t rowSel = (uint32_t)(lane & 15) * TP64;
    const uint32_t colSel = (uint32_t)((lane >> 4) << 4);
    const uint32_t aOff = (uint32_t)(wr * 64) * TP64 + rowSel + colSel;
    const uint32_t bOff = (uint32_t)(wc * 32) * TP64 + rowSel + colSel;

    float acc[4][4][4];
    #pragma unroll
    for (int mf = 0; mf < 4; mf++)
        #pragma unroll
        for (int nf = 0; nf < 4; nf++)
            #pragma unroll
            for (int e = 0; e < 4; e++) acc[mf][nf][e] = 0.0f;

    // prologue: chunk 0
    load_tile64(sb + MBUF(0, 0), Xhi + (size_t)iBase * D_IN, D_IN, tid);
    load_tile64(sb + MBUF(0, 1), Xlo + (size_t)iBase * D_IN, D_IN, tid);
    load_tile64(sb + MBUF(0, 2), Whi + (size_t)nBase * D_IN, D_IN, tid);
    load_tile64(sb + MBUF(0, 3), Wlo + (size_t)nBase * D_IN, D_IN, tid);
    cp_commit();

    for (int kc = 0; kc < 8; kc++) {
        const int buf = kc & 1;
        cp_wait0();
        __syncthreads();
        if (kc < 7) {
            const int k1 = (kc + 1) * 64;
            load_tile64(sb + MBUF(buf ^ 1, 0), Xhi + (size_t)iBase * D_IN + k1, D_IN, tid);
            load_tile64(sb + MBUF(buf ^ 1, 1), Xlo + (size_t)iBase * D_IN + k1, D_IN, tid);
            load_tile64(sb + MBUF(buf ^ 1, 2), Whi + (size_t)nBase * D_IN + k1, D_IN, tid);
            load_tile64(sb + MBUF(buf ^ 1, 3), Wlo + (size_t)nBase * D_IN + k1, D_IN, tid);
            cp_commit();
        }
        mma_pass64(acc, sb + MBUF(buf, 0) + aOff, sb + MBUF(buf, 2) + bOff);
        mma_pass64(acc, sb + MBUF(buf, 0) + aOff, sb + MBUF(buf, 3) + bOff);
        mma_pass64(acc, sb + MBUF(buf, 1) + aOff, sb + MBUF(buf, 2) + bOff);
    }

    #pragma unroll
    for (int mf = 0; mf < 4; mf++) {
        const int r0 = iBase + wr * 64 + mf * 16 + group;
        #pragma unroll
        for (int nf = 0; nf < 4; nf++) {
            const int c0 = nBase + wc * 32 + nf * 8 + tig * 2;
            const float bb0 = bias[c0], bb1 = bias[c0 + 1];
            #pragma unroll
            for (int rr = 0; rr < 2; rr++) {
                const int r = r0 + rr * 8;
                float v0 = fmaxf(acc[mf][nf][rr * 2 + 0] + bb0, 0.0f);
                float v1 = fmaxf(acc[mf][nf][rr * 2 + 1] + bb1, 0.0f);
                __nv_bfloat16 h0, h1, l0, l1;
                bsplit(v0, h0, l0); bsplit(v1, h1, l1);
                *(__nv_bfloat162*)(g_Hhi[h] + (size_t)r * D_HID + c0) = __nv_bfloat162(h0, h1);
                *(__nv_bfloat162*)(g_Hlo[h] + (size_t)r * D_HID + c0) = __nv_bfloat162(l0, l1);
            }
        }
    }
}

// Y = H @ W2 + b2 (fp32) + fused per-CTA whitening partial sums. grid (64, 1, 3)
__global__ __launch_bounds__(256, 1) void mlp_gemmB(BArgs ba) {
    extern __shared__ unsigned char smem[];
    __shared__ float scs[D_OUT][2];
    __shared__ float scq[D_OUT][2];
    uint32_t sb = smem_u32(smem);
    const int tid = threadIdx.x, lane = tid & 31, w = tid >> 5;
    const int wr = w >> 2, wc = w & 3, group = lane >> 2, tig = lane & 3;
    const int h = blockIdx.z;
    const int iBase = blockIdx.x * 128;
    const __nv_bfloat16* Ahi = g_Hhi[h];
    const __nv_bfloat16* Alo = g_Hlo[h];
    const __nv_bfloat16* Whi = g_W2t_hi[h];
    const __nv_bfloat16* Wlo = g_W2t_lo[h];
    const float* __restrict__ bias = ba.b2[h];

    const uint32_t rowSel = (uint32_t)(lane & 15) * TP64;
    const uint32_t colSel = (uint32_t)((lane >> 4) << 4);
    const uint32_t aOff = (uint32_t)(wr * 64) * TP64 + rowSel + colSel;
    const uint32_t bOff = (uint32_t)(wc * 32) * TP64 + rowSel + colSel;

    float acc[4][4][4];
    #pragma unroll
    for (int mf = 0; mf < 4; mf++)
        #pragma unroll
        for (int nf = 0; nf < 4; nf++)
            #pragma unroll
            for (int e = 0; e < 4; e++) acc[mf][nf][e] = 0.0f;

    load_tile64(sb + MBUF(0, 0), Ahi + (size_t)iBase * D_HID, D_HID, tid);
    load_tile64(sb + MBUF(0, 1), Alo + (size_t)iBase * D_HID, D_HID, tid);
    load_tile64(sb + MBUF(0, 2), Whi, D_HID, tid);
    load_tile64(sb + MBUF(0, 3), Wlo, D_HID, tid);
    cp_commit();

    for (int kc = 0; kc < 4; kc++) {
        const int buf = kc & 1;
        cp_wait0();
        __syncthreads();
        if (kc < 3) {
            const int k1 = (kc + 1) * 64;
            load_tile64(sb + MBUF(buf ^ 1, 0), Ahi + (size_t)iBase * D_HID + k1, D_HID, tid);
            load_tile64(sb + MBUF(buf ^ 1, 1), Alo + (size_t)iBase * D_HID + k1, D_HID, tid);
            load_tile64(sb + MBUF(buf ^ 1, 2), Whi + k1, D_HID, tid);
            load_tile64(sb + MBUF(buf ^ 1, 3), Wlo + k1, D_HID, tid);
            cp_commit();
        }
        mma_pass64(acc, sb + MBUF(buf, 0) + aOff, sb + MBUF(buf, 2) + bOff);
        mma_pass64(acc, sb + MBUF(buf, 0) + aOff, sb + MBUF(buf, 3) + bOff);
        mma_pass64(acc, sb + MBUF(buf, 1) + aOff, sb + MBUF(buf, 2) + bOff);
    }

    float cs[8] = {0, 0, 0, 0, 0, 0, 0, 0};
    float cq[8] = {0, 0, 0, 0, 0, 0, 0, 0};

    #pragma unroll
    for (int mf = 0; mf < 4; mf++) {
        const int r0 = iBase + wr * 64 + mf * 16 + group;
        #pragma unroll
        for (int nf = 0; nf < 4; nf++) {
            const int c0 = wc * 32 + nf * 8 + tig * 2;
            const float bb0 = bias[c0], bb1 = bias[c0 + 1];
            #pragma unroll
            for (int rr = 0; rr < 2; rr++) {
                const int r = r0 + rr * 8;
                float v0 = acc[mf][nf][rr * 2 + 0] + bb0;
                float v1 = acc[mf][nf][rr * 2 + 1] + bb1;
                *(float2*)(g_Y[h] + (size_t)r * D_OUT + c0) = make_float2(v0, v1);
                cs[nf * 2 + 0] += v0; cq[nf * 2 + 0] = fmaf(v0, v0, cq[nf * 2 + 0]);
                cs[nf * 2 + 1] += v1; cq[nf * 2 + 1] = fmaf(v1, v1, cq[nf * 2 + 1]);
            }
        }
    }
    // reduce over rows within warp (butterfly over group bits = lane bits 2..4)
    #pragma unroll
    for (int s = 0; s < 8; s++) {
        #pragma unroll
        for (int off = 4; off <= 16; off <<= 1) {
            cs[s] += __shfl_xor_sync(0xFFFFFFFFu, cs[s], off);
            cq[s] += __shfl_xor_sync(0xFFFFFFFFu, cq[s], off);
        }
    }
    if (group == 0) {
        #pragma unroll
        for (int nf = 0; nf < 4; nf++) {
            #pragma unroll
            for (int e = 0; e < 2; e++) {
                int c = wc * 32 + nf * 8 + tig * 2 + e;
                scs[c][wr] = cs[nf * 2 + e];
                scq[c][wr] = cq[nf * 2 + e];
            }
        }
    }
    __syncthreads();
    if (tid < D_OUT) {
        g_psum[h][blockIdx.x][tid] = scs[tid][0] + scs[tid][1];
        g_psq[h][blockIdx.x][tid]  = scq[tid][0] + scq[tid][1];
    }
}

// ---------------- stage 1b: whitening stats finalize ----------------
__global__ void stats_final() {
    __shared__ double ssum[4][D_OUT];
    __shared__ double ssq[4][D_OUT];
    int set = blockIdx.x;
    int t = threadIdx.x & 127;
    int part = threadIdx.x >> 7;     // 0..3, 16 blocks each
    double s = 0.0, q = 0.0;
    for (int b = 0; b < 16; b++) {
        s += (double)g_psum[set][part * 16 + b][t];
        q += (double)g_psq[set][part * 16 + b][t];
    }
    ssum[part][t] = s; ssq[part][t] = q;
    __syncthreads();
    if (part == 0) {
        double S = ssum[0][t] + ssum[1][t] + ssum[2][t] + ssum[3][t];
        double Q = ssq[0][t] + ssq[1][t] + ssq[2][t] + ssq[3][t];
        double n = (double)BATCH;
        double mean = S / n;
        double var = (Q - S * S / n) / (n - 1.0);
        if (var < 0.0) var = 0.0;
        g_mean[set][t] = (float)mean;
        g_sd[set][t] = (float)(sqrt(var) + 1e-5);
    }
}

// ---------------- stage 1c: fused whiten + L2 normalize + pos dots + scaled bf16 ----------------
__global__ void norm_pos() {
    __shared__ float wss[4][3];
    __shared__ float wpp[4][3];
    int i = blockIdx.x;
    int t = threadIdx.x;
    int wid = t >> 5, lane = t & 31;

    float z[3], ssl[3];
    #pragma unroll
    for (int s = 0; s < 3; s++) {
        float v = (g_Y[s][i * D_OUT + t] - g_mean[s][t]) / g_sd[s][t];
        z[s] = v;
        ssl[s] = v * v;
    }
    #pragma unroll
    for (int s = 0; s < 3; s++)
        #pragma unroll
        for (int o = 16; o > 0; o >>= 1) ssl[s] += __shfl_xor_sync(0xFFFFFFFFu, ssl[s], o);
    if (lane == 0) { wss[wid][0] = ssl[0]; wss[wid][1] = ssl[1]; wss[wid][2] = ssl[2]; }
    __syncthreads();
    #pragma unroll
    for (int s = 0; s < 3; s++) {
        float tot = wss[0][s] + wss[1][s] + wss[2][s] + wss[3][s];
        float nrm = fmaxf(sqrtf(tot), 1e-12f);
        z[s] /= nrm;
    }
    // exact fp32 positive logits: 0:(B,E) 1:(B,F) 2:(E,F)
    float p[3] = { z[0] * z[1], z[0] * z[2], z[1] * z[2] };
    #pragma unroll
    for (int s = 0; s < 3; s++)
        #pragma unroll
        for (int o = 16; o > 0; o >>= 1) p[s] += __shfl_xor_sync(0xFFFFFFFFu, p[s], o);
    if (lane == 0) { wpp[wid][0] = p[0]; wpp[wid][1] = p[1]; wpp[wid][2] = p[2]; }
    __syncthreads();
    if (t == 0) {
        #pragma unroll
        for (int s = 0; s < 3; s++)
            g_pos[s][i] = wpp[0][s] + wpp[1][s] + wpp[2][s] + wpp[3][s];
    }
    #pragma unroll
    for (int s = 0; s < 3; s++)
        g_Zhi[s][i * D_OUT + t] = __float2bfloat16(z[s] * ZSCALE);
}

// ---------------- stage 2: hi-only bf16 gram, log2-domain, pipe-balanced exp ----------------
#define SOFF_A    0
#define SOFF_B(b) (TILE_BYTES + (b) * TILE_BYTES)
#define SOFF_RED  (3 * TILE_BYTES)
#define GRAM_SMEM (3 * TILE_BYTES + 2048)   // 106496

__global__ __launch_bounds__(256, 2) void gram_kernel() {
    extern __shared__ unsigned char smem[];
    uint32_t sb = smem_u32(smem);
    float* red = (float*)(smem + SOFF_RED);

    const int tid = threadIdx.x, lane = tid & 31, w = tid >> 5;
    const int wr = w >> 2, wc = w & 3, group = lane >> 2, tig = lane & 3;

    const int g = blockIdx.z;
    const __nv_bfloat16* __restrict__ A = g_Zhi[c_ga[g]];
    const __nv_bfloat16* __restrict__ B = g_Zhi[c_gb[g]];
    const int same = c_same[g];
    const int iBase = blockIdx.x * GTILE;
    const int chunk = blockIdx.y;
    const int jChunk0 = chunk * CHUNKJ;

    load_tile(sb + SOFF_A, A + (size_t)iBase * D_OUT, D_OUT, tid);
    load_tile(sb + SOFF_B(0), B + (size_t)jChunk0 * D_OUT, D_OUT, tid);
    cp_commit();

    const uint32_t rowSel = (uint32_t)(lane & 15) * TPITCH;
    const uint32_t colSel = (uint32_t)((lane >> 4) << 4);
    const uint32_t aBase = sb + SOFF_A + (uint32_t)(wr * 64) * TPITCH + rowSel + colSel;
    const uint32_t bOff = (uint32_t)(wc * 32) * TPITCH + rowSel + colSel;

    float rsacc[8] = {0, 0, 0, 0, 0, 0, 0, 0};

    for (int jt = 0; jt < CHUNKJ / GTILE; jt++) {
        const int buf = jt & 1;
        const int jBase = jChunk0 + jt * GTILE;

        cp_wait0();
        __syncthreads();

        if (jt + 1 < CHUNKJ / GTILE) {
            load_tile(sb + SOFF_B(buf ^ 1), B + (size_t)(jBase + GTILE) * D_OUT, D_OUT, tid);
            cp_commit();
        }

        const uint32_t bBase = sb + SOFF_B(buf) + bOff;

        float acc[4][4][4];
        #pragma unroll
        for (int mf = 0; mf < 4; mf++)
            #pragma unroll
            for (int nf = 0; nf < 4; nf++)
                #pragma unroll
                for (int e = 0; e < 4; e++) acc[mf][nf][e] = 0.0f;

        mma_pass(acc, aBase, bBase);

        // epilogue: acc is log2-domain logit; mf==0 on FMA pipe, mf 1..3 on MUFU
        if (!(same && jBase == iBase)) {
            #pragma unroll
            for (int mf = 0; mf < 4; mf++) {
                float s0 = 0.0f, s1 = 0.0f;
                #pragma unroll
                for (int nf = 0; nf < 4; nf++) {
                    if (mf == 0) {
                        s0 += tex2(acc[mf][nf][0]) + tex2(acc[mf][nf][1]);
                        s1 += tex2(acc[mf][nf][2]) + tex2(acc[mf][nf][3]);
                    } else {
                        s0 += ex2(acc[mf][nf][0]) + ex2(acc[mf][nf][1]);
                        s1 += ex2(acc[mf][nf][2]) + ex2(acc[mf][nf][3]);
                    }
                }
                rsacc[mf * 2 + 0] += s0;
                rsacc[mf * 2 + 1] += s1;
            }
        } else {
            #pragma unroll
            for (int mf = 0; mf < 4; mf++) {
                const int r0 = wr * 64 + mf * 16 + group;
                float s0 = 0.0f, s1 = 0.0f;
                #pragma unroll
                for (int nf = 0; nf < 4; nf++) {
                    const int c0 = wc * 32 + nf * 8 + tig * 2;
                    #pragma unroll
                    for (int e = 0; e < 4; e++) {
                        const int r = r0 + (e >> 1) * 8;
                        const int c = c0 + (e & 1);
                        float ev = (r == c) ? 1.0f : ex2(acc[mf][nf][e]);
                        if (e < 2) s0 += ev; else s1 += ev;
                    }
                }
                rsacc[mf * 2 + 0] += s0;
                rsacc[mf * 2 + 1] += s1;
            }
        }
    }

    #pragma unroll
    for (int s = 0; s < 8; s++) {
        float v = rsacc[s];
        v += __shfl_xor_sync(0xFFFFFFFFu, v, 1);
        v += __shfl_xor_sync(0xFFFFFFFFu, v, 2);
        rsacc[s] = v;
    }
    __syncthreads();
    if (tig == 0) {
        #pragma unroll
        for (int mf = 0; mf < 4; mf++) {
            #pragma unroll
            for (int e = 0; e < 2; e++) {
                int r = wr * 64 + mf * 16 + group + e * 8;
                red[r * 4 + wc] = rsacc[mf * 2 + e];
            }
        }
    }
    __syncthreads();
    if (tid < 128) {
        float s = red[tid * 4 + 0] + red[tid * 4 + 1] + red[tid * 4 + 2] + red[tid * 4 + 3];
        g_rspart[g][chunk][iBase + tid] = s;
    }
}

// ---------------- stage 3: loss (two-stage, deterministic) ----------------
__global__ void loss_part() {
    __shared__ double sred[128];
    int t = threadIdx.x;
    int i = blockIdx.x * 128 + t;
    float rsBB = 0, rsEE = 0, rsBE = 0, rsBF = 0, rsEF = 0;
    #pragma unroll
    for (int c = 0; c < NCHUNK; c++) {
        rsBB += g_rspart[0][c][i];
        rsEE += g_rspart[1][c][i];
        rsBE += g_rspart[2][c][i];
        rsBF += g_rspart[3][c][i];
        rsEF += g_rspart[4][c][i];
    }
    double acc = 0.0;
    acc += (double)logf(rsBB + rsBE) - (double)g_pos[0][i];
    acc += (double)logf(rsBB + rsBF) - (double)g_pos[1][i];
    acc += (double)logf(rsEE + rsEF) - (double)g_pos[2][i];
    sred[t] = acc;
    __syncthreads();
    for (int s = 64; s > 0; s >>= 1) {
        if (t < s) sred[t] += sred[t + s];
        __syncthreads();
    }
    if (t == 0) g_lpart[blockIdx.x] = sred[0];
}

__global__ void loss_final(float* __restrict__ out) {
    __shared__ double s[64];
    int t = threadIdx.x;
    s[t] = g_lpart[t];
    __syncthreads();
    for (int k = 32; k > 0; k >>= 1) {
        if (t < k) s[t] += s[t + k];
        __syncthreads();
    }
    if (t == 0) out[0] = (float)(s[0] / (3.0 * (double)BATCH));
}

// ---------------- launch ----------------
extern "C" void kernel_launch(void* const* d_in, const int* in_sizes, int n_in,
                              void* d_out, int out_size)
{
    static bool inited = false;
    if (!inited) {
        cudaFuncSetAttribute(gram_kernel, cudaFuncAttributeMaxDynamicSharedMemorySize, GRAM_SMEM);
        cudaFuncSetAttribute(mlp_gemmA, cudaFuncAttributeMaxDynamicSharedMemorySize, MLP_SMEM);
        cudaFuncSetAttribute(mlp_gemmB, cudaFuncAttributeMaxDynamicSharedMemorySize, MLP_SMEM);
        inited = true;
    }

    WArgs wa;
    BArgs ba;
    for (int m = 0; m < 3; m++) {
        wa.W1[m] = (const float*)d_in[3 + 4 * m];
        ba.b1[m] = (const float*)d_in[4 + 4 * m];
        wa.W2[m] = (const float*)d_in[5 + 4 * m];
        ba.b2[m] = (const float*)d_in[6 + 4 * m];
    }

    split_x<<<dim3(BATCH * D_IN / 1024, 3), 256>>>(
        (const float*)d_in[0], (const float*)d_in[1], (const float*)d_in[2]);
    split_w<<<dim3((D_IN * D_HID + D_HID * D_OUT) / 256, 3), 256>>>(wa);

    mlp_gemmA<<<dim3(BATCH / 128, 2, 3), 256, MLP_SMEM>>>(ba);
    mlp_gemmB<<<dim3(BATCH / 128, 1, 3), 256, MLP_SMEM>>>(ba);

    stats_final<<<3, 512>>>();
    norm_pos<<<BATCH, 128>>>();

    gram_kernel<<<dim3(BATCH / GTILE, NCHUNK, 5), 256, GRAM_SMEM>>>();

    loss_part<<<64, 128>>>();
    loss_final<<<1, 64>>>((float*)d_out);
}

// round 11
// speedup vs baseline: 8.3971x; 1.1090x over previous
#include <cuda_runtime.h>
#include <cuda_bf16.h>
#include <cmath>
#include <cstdint>

// ---------------- problem dims ----------------
#define BATCH   8192
#define D_IN    512
#define D_HID   256
#define D_OUT   128

#define GTILE   128
#define NCHUNK  4

// sqrt(log2(e)): Zhi scaled by this => gram accumulators are log2-domain
#define ZSCALE  1.2011224087864498f
#define LN2F    0.6931471805599453f

// ---------------- device scratch ----------------
__device__ __align__(16) __nv_bfloat16 g_xhi[3][BATCH * D_IN];
__device__ __align__(16) __nv_bfloat16 g_xlo[3][BATCH * D_IN];
__device__ __align__(16) __nv_bfloat16 g_W1t_hi[3][D_HID * D_IN];
__device__ __align__(16) __nv_bfloat16 g_W1t_lo[3][D_HID * D_IN];
__device__ __align__(16) __nv_bfloat16 g_W2t_hi[3][D_OUT * D_HID];
__device__ __align__(16) __nv_bfloat16 g_W2t_lo[3][D_OUT * D_HID];
__device__ __align__(16) __nv_bfloat16 g_Hhi[3][BATCH * D_HID];
__device__ __align__(16) __nv_bfloat16 g_Hlo[3][BATCH * D_HID];
__device__ float g_Y[3][BATCH * D_OUT];
__device__ __align__(16) __nv_bfloat16 g_Zhi[3][BATCH * D_OUT];
__device__ float g_psum[3][64][D_OUT];
__device__ float g_psq[3][64][D_OUT];
__device__ float g_mean[3][D_OUT];
__device__ float g_sd[3][D_OUT];
__device__ float g_rspart[5][NCHUNK][BATCH];   // row partials (chunk slots)
__device__ float g_colpart[2][64][BATCH];      // sym-gram col partials (slot = source i-tile)
__device__ float g_pos[3][BATCH];
__device__ double g_lpart[64];

// gram configs: 0:BB 1:EE 2:BE 3:BF 4:EF
__constant__ int c_ga[5]   = {0, 1, 0, 0, 1};
__constant__ int c_gb[5]   = {0, 1, 1, 2, 2};
__constant__ int c_same[5] = {1, 1, 0, 0, 0};

// ---------------- PTX helpers (sm_80-level only) ----------------
__device__ __forceinline__ uint32_t smem_u32(const void* p) {
    return (uint32_t)__cvta_generic_to_shared(p);
}
__device__ __forceinline__ void cp16(uint32_t dst, const void* src) {
    asm volatile("cp.async.cg.shared.global [%0], [%1], 16;"
                 :: "r"(dst), "l"(__cvta_generic_to_global(src)) : "memory");
}
__device__ __forceinline__ void cp_commit() {
    asm volatile("cp.async.commit_group;" ::: "memory");
}
__device__ __forceinline__ void cp_wait0() {
    asm volatile("cp.async.wait_group 0;" ::: "memory");
}

#define LDSM_X4(r, addr) \
    asm volatile("ldmatrix.sync.aligned.m8n8.x4.shared.b16 {%0,%1,%2,%3}, [%4];" \
        : "=r"((r)[0]), "=r"((r)[1]), "=r"((r)[2]), "=r"((r)[3]) : "r"(addr))

#define MMA16816(d, a, b0, b1) \
    asm volatile("mma.sync.aligned.m16n8k16.row.col.f32.bf16.bf16.f32 " \
        "{%0,%1,%2,%3}, {%4,%5,%6,%7}, {%8,%9}, {%0,%1,%2,%3};" \
        : "+f"((d)[0]), "+f"((d)[1]), "+f"((d)[2]), "+f"((d)[3]) \
        : "r"((a)[0]), "r"((a)[1]), "r"((a)[2]), "r"((a)[3]), "r"(b0), "r"(b1))

__device__ __forceinline__ void bsplit(float v, __nv_bfloat16& hi, __nv_bfloat16& lo) {
    hi = __float2bfloat16(v);
    lo = __float2bfloat16(v - __bfloat162float(hi));
}

// MUFU 2^x
__device__ __forceinline__ float ex2(float x) {
    float y;
    asm("ex2.approx.f32 %0, %1;" : "=f"(y) : "f"(x));
    return y;
}
// FMA-pipe 2^x via e^(x ln2), |x| <= ~1.52 -> |t| <= 1.06
__device__ __forceinline__ float tex2(float x) {
    float t = x * LN2F;
    float r = 2.48015873e-5f;
    r = fmaf(r, t, 1.98412698e-4f);
    r = fmaf(r, t, 1.38888889e-3f);
    r = fmaf(r, t, 8.33333333e-3f);
    r = fmaf(r, t, 4.16666667e-2f);
    r = fmaf(r, t, 1.66666667e-1f);
    r = fmaf(r, t, 0.5f);
    r = fmaf(r, t, 1.0f);
    r = fmaf(r, t, 1.0f);
    return r;
}

// ---------------- smem tile geometry ----------------
#define TPITCH     272
#define TILE_BYTES (128 * TPITCH)           // 34816
#define TP64       144
#define T64B       (128 * TP64)             // 18432

__device__ __forceinline__ void load_tile(uint32_t dst, const __nv_bfloat16* src,
                                          int strideElems, int tid) {
    #pragma unroll
    for (int idx = tid; idx < 2048; idx += 256) {
        int r = idx >> 4, c = idx & 15;
        cp16(dst + r * TPITCH + c * 16, src + r * strideElems + c * 8);
    }
}
__device__ __forceinline__ void load_tile64(uint32_t dst, const __nv_bfloat16* src,
                                            int strideElems, int tid) {
    #pragma unroll
    for (int idx = tid; idx < 1024; idx += 256) {
        int r = idx >> 3, c = idx & 7;
        cp16(dst + r * TP64 + c * 16, src + r * strideElems + c * 8);
    }
}

// K=128 mma pass (gram)
__device__ __forceinline__ void mma_pass(float acc[4][4][4], uint32_t aBase, uint32_t bBase) {
    #pragma unroll
    for (int ks = 0; ks < 8; ks++) {
        const uint32_t kb = (uint32_t)ks * 32;
        uint32_t a[4][4], b[2][4];
        #pragma unroll
        for (int mf = 0; mf < 4; mf++)
            LDSM_X4(a[mf], aBase + (uint32_t)(mf * 16) * TPITCH + kb);
        #pragma unroll
        for (int ng = 0; ng < 2; ng++)
            LDSM_X4(b[ng], bBase + (uint32_t)(ng * 16) * TPITCH + kb);
        #pragma unroll
        for (int mf = 0; mf < 4; mf++) {
            #pragma unroll
            for (int nf = 0; nf < 4; nf++) {
                const int ng = nf >> 1, od = nf & 1;
                MMA16816(acc[mf][nf], a[mf], b[ng][od], b[ng][od + 2]);
            }
        }
    }
}
// K=64 mma pass (MLP)
__device__ __forceinline__ void mma_pass64(float acc[4][4][4], uint32_t aBase, uint32_t bBase) {
    #pragma unroll
    for (int ks = 0; ks < 4; ks++) {
        const uint32_t kb = (uint32_t)ks * 32;
        uint32_t a[4][4], b[2][4];
        #pragma unroll
        for (int mf = 0; mf < 4; mf++)
            LDSM_X4(a[mf], aBase + (uint32_t)(mf * 16) * TP64 + kb);
        #pragma unroll
        for (int ng = 0; ng < 2; ng++)
            LDSM_X4(b[ng], bBase + (uint32_t)(ng * 16) * TP64 + kb);
        #pragma unroll
        for (int mf = 0; mf < 4; mf++) {
            #pragma unroll
            for (int nf = 0; nf < 4; nf++) {
                const int ng = nf >> 1, od = nf & 1;
                MMA16816(acc[mf][nf], a[mf], b[ng][od], b[ng][od + 2]);
            }
        }
    }
}

// ---------------- stage 0: bf16 hi/lo splits ----------------
__global__ void split_x(const float* xB, const float* xE, const float* xF) {
    int h = blockIdx.y;
    const float* x = (h == 0) ? xB : ((h == 1) ? xE : xF);
    int base = (blockIdx.x * 256 + threadIdx.x) * 4;
    float4 v = *(const float4*)(x + base);
    __nv_bfloat16 h0, h1, h2, h3, l0, l1, l2, l3;
    bsplit(v.x, h0, l0); bsplit(v.y, h1, l1);
    bsplit(v.z, h2, l2); bsplit(v.w, h3, l3);
    __nv_bfloat162* dh = (__nv_bfloat162*)(g_xhi[h] + base);
    __nv_bfloat162* dl = (__nv_bfloat162*)(g_xlo[h] + base);
    dh[0] = __nv_bfloat162(h0, h1); dh[1] = __nv_bfloat162(h2, h3);
    dl[0] = __nv_bfloat162(l0, l1); dl[1] = __nv_bfloat162(l2, l3);
}

struct WArgs { const float* W1[3]; const float* W2[3]; };

__global__ void split_w(WArgs wa) {
    int h = blockIdx.y;
    int idx = blockIdx.x * 256 + threadIdx.x;
    if (idx < D_IN * D_HID) {
        int k = idx >> 8, n = idx & 255;
        __nv_bfloat16 hi, lo;
        bsplit(wa.W1[h][idx], hi, lo);
        g_W1t_hi[h][n * D_IN + k] = hi;
        g_W1t_lo[h][n * D_IN + k] = lo;
    } else {
        int i2 = idx - D_IN * D_HID;
        int k = i2 >> 7, n = i2 & 127;
        __nv_bfloat16 hi, lo;
        bsplit(wa.W2[h][i2], hi, lo);
        g_W2t_hi[h][n * D_HID + k] = hi;
        g_W2t_lo[h][n * D_HID + k] = lo;
    }
}

// ---------------- stage 1: tensor-core MLP GEMMs ----------------
struct BArgs { const float* b1[3]; const float* b2[3]; };

#define MBUF(buf, which) ((uint32_t)(((buf) * 4 + (which)) * T64B))
#define MLP_SMEM (8 * T64B)   // 147456

// H = relu(x @ W1 + b1) -> bf16 hi/lo. grid (64, 2, 3)
__global__ __launch_bounds__(256, 1) void mlp_gemmA(BArgs ba) {
    extern __shared__ unsigned char smem[];
    uint32_t sb = smem_u32(smem);
    const int tid = threadIdx.x, lane = tid & 31, w = tid >> 5;
    const int wr = w >> 2, wc = w & 3, group = lane >> 2, tig = lane & 3;
    const int h = blockIdx.z;
    const int iBase = blockIdx.x * 128, nBase = blockIdx.y * 128;
    const __nv_bfloat16* Xhi = g_xhi[h];
    const __nv_bfloat16* Xlo = g_xlo[h];
    const __nv_bfloat16* Whi = g_W1t_hi[h];
    const __nv_bfloat16* Wlo = g_W1t_lo[h];
    const float* __restrict__ bias = ba.b1[h];

    const uint32_t rowSel = (uint32_t)(lane & 15) * TP64;
    const uint32_t colSel = (uint32_t)((lane >> 4) << 4);
    const uint32_t aOff = (uint32_t)(wr * 64) * TP64 + rowSel + colSel;
    const uint32_t bOff = (uint32_t)(wc * 32) * TP64 + rowSel + colSel;

    float acc[4][4][4];
    #pragma unroll
    for (int mf = 0; mf < 4; mf++)
        #pragma unroll
        for (int nf = 0; nf < 4; nf++)
            #pragma unroll
            for (int e = 0; e < 4; e++) acc[mf][nf][e] = 0.0f;

    load_tile64(sb + MBUF(0, 0), Xhi + (size_t)iBase * D_IN, D_IN, tid);
    load_tile64(sb + MBUF(0, 1), Xlo + (size_t)iBase * D_IN, D_IN, tid);
    load_tile64(sb + MBUF(0, 2), Whi + (size_t)nBase * D_IN, D_IN, tid);
    load_tile64(sb + MBUF(0, 3), Wlo + (size_t)nBase * D_IN, D_IN, tid);
    cp_commit();

    for (int kc = 0; kc < 8; kc++) {
        const int buf = kc & 1;
        cp_wait0();
        __syncthreads();
        if (kc < 7) {
            const int k1 = (kc + 1) * 64;
            load_tile64(sb + MBUF(buf ^ 1, 0), Xhi + (size_t)iBase * D_IN + k1, D_IN, tid);
            load_tile64(sb + MBUF(buf ^ 1, 1), Xlo + (size_t)iBase * D_IN + k1, D_IN, tid);
            load_tile64(sb + MBUF(buf ^ 1, 2), Whi + (size_t)nBase * D_IN + k1, D_IN, tid);
            load_tile64(sb + MBUF(buf ^ 1, 3), Wlo + (size_t)nBase * D_IN + k1, D_IN, tid);
            cp_commit();
        }
        mma_pass64(acc, sb + MBUF(buf, 0) + aOff, sb + MBUF(buf, 2) + bOff);
        mma_pass64(acc, sb + MBUF(buf, 0) + aOff, sb + MBUF(buf, 3) + bOff);
        mma_pass64(acc, sb + MBUF(buf, 1) + aOff, sb + MBUF(buf, 2) + bOff);
    }

    #pragma unroll
    for (int mf = 0; mf < 4; mf++) {
        const int r0 = iBase + wr * 64 + mf * 16 + group;
        #pragma unroll
        for (int nf = 0; nf < 4; nf++) {
            const int c0 = nBase + wc * 32 + nf * 8 + tig * 2;
            const float bb0 = bias[c0], bb1 = bias[c0 + 1];
            #pragma unroll
            for (int rr = 0; rr < 2; rr++) {
                const int r = r0 + rr * 8;
                float v0 = fmaxf(acc[mf][nf][rr * 2 + 0] + bb0, 0.0f);
                float v1 = fmaxf(acc[mf][nf][rr * 2 + 1] + bb1, 0.0f);
                __nv_bfloat16 h0, h1, l0, l1;
                bsplit(v0, h0, l0); bsplit(v1, h1, l1);
                *(__nv_bfloat162*)(g_Hhi[h] + (size_t)r * D_HID + c0) = __nv_bfloat162(h0, h1);
                *(__nv_bfloat162*)(g_Hlo[h] + (size_t)r * D_HID + c0) = __nv_bfloat162(l0, l1);
            }
        }
    }
}

// Y = H @ W2 + b2 (fp32) + fused per-CTA whitening partial sums. grid (64, 1, 3)
__global__ __launch_bounds__(256, 1) void mlp_gemmB(BArgs ba) {
    extern __shared__ unsigned char smem[];
    __shared__ float scs[D_OUT][2];
    __shared__ float scq[D_OUT][2];
    uint32_t sb = smem_u32(smem);
    const int tid = threadIdx.x, lane = tid & 31, w = tid >> 5;
    const int wr = w >> 2, wc = w & 3, group = lane >> 2, tig = lane & 3;
    const int h = blockIdx.z;
    const int iBase = blockIdx.x * 128;
    const __nv_bfloat16* Ahi = g_Hhi[h];
    const __nv_bfloat16* Alo = g_Hlo[h];
    const __nv_bfloat16* Whi = g_W2t_hi[h];
    const __nv_bfloat16* Wlo = g_W2t_lo[h];
    const float* __restrict__ bias = ba.b2[h];

    const uint32_t rowSel = (uint32_t)(lane & 15) * TP64;
    const uint32_t colSel = (uint32_t)((lane >> 4) << 4);
    const uint32_t aOff = (uint32_t)(wr * 64) * TP64 + rowSel + colSel;
    const uint32_t bOff = (uint32_t)(wc * 32) * TP64 + rowSel + colSel;

    float acc[4][4][4];
    #pragma unroll
    for (int mf = 0; mf < 4; mf++)
        #pragma unroll
        for (int nf = 0; nf < 4; nf++)
            #pragma unroll
            for (int e = 0; e < 4; e++) acc[mf][nf][e] = 0.0f;

    load_tile64(sb + MBUF(0, 0), Ahi + (size_t)iBase * D_HID, D_HID, tid);
    load_tile64(sb + MBUF(0, 1), Alo + (size_t)iBase * D_HID, D_HID, tid);
    load_tile64(sb + MBUF(0, 2), Whi, D_HID, tid);
    load_tile64(sb + MBUF(0, 3), Wlo, D_HID, tid);
    cp_commit();

    for (int kc = 0; kc < 4; kc++) {
        const int buf = kc & 1;
        cp_wait0();
        __syncthreads();
        if (kc < 3) {
            const int k1 = (kc + 1) * 64;
            load_tile64(sb + MBUF(buf ^ 1, 0), Ahi + (size_t)iBase * D_HID + k1, D_HID, tid);
            load_tile64(sb + MBUF(buf ^ 1, 1), Alo + (size_t)iBase * D_HID + k1, D_HID, tid);
            load_tile64(sb + MBUF(buf ^ 1, 2), Whi + k1, D_HID, tid);
            load_tile64(sb + MBUF(buf ^ 1, 3), Wlo + k1, D_HID, tid);
            cp_commit();
        }
        mma_pass64(acc, sb + MBUF(buf, 0) + aOff, sb + MBUF(buf, 2) + bOff);
        mma_pass64(acc, sb + MBUF(buf, 0) + aOff, sb + MBUF(buf, 3) + bOff);
        mma_pass64(acc, sb + MBUF(buf, 1) + aOff, sb + MBUF(buf, 2) + bOff);
    }

    float cs[8] = {0, 0, 0, 0, 0, 0, 0, 0};
    float cq[8] = {0, 0, 0, 0, 0, 0, 0, 0};

    #pragma unroll
    for (int mf = 0; mf < 4; mf++) {
        const int r0 = iBase + wr * 64 + mf * 16 + group;
        #pragma unroll
        for (int nf = 0; nf < 4; nf++) {
            const int c0 = wc * 32 + nf * 8 + tig * 2;
            const float bb0 = bias[c0], bb1 = bias[c0 + 1];
            #pragma unroll
            for (int rr = 0; rr < 2; rr++) {
                const int r = r0 + rr * 8;
                float v0 = acc[mf][nf][rr * 2 + 0] + bb0;
                float v1 = acc[mf][nf][rr * 2 + 1] + bb1;
                *(float2*)(g_Y[h] + (size_t)r * D_OUT + c0) = make_float2(v0, v1);
                cs[nf * 2 + 0] += v0; cq[nf * 2 + 0] = fmaf(v0, v0, cq[nf * 2 + 0]);
                cs[nf * 2 + 1] += v1; cq[nf * 2 + 1] = fmaf(v1, v1, cq[nf * 2 + 1]);
            }
        }
    }
    #pragma unroll
    for (int s = 0; s < 8; s++) {
        #pragma unroll
        for (int off = 4; off <= 16; off <<= 1) {
            cs[s] += __shfl_xor_sync(0xFFFFFFFFu, cs[s], off);
            cq[s] += __shfl_xor_sync(0xFFFFFFFFu, cq[s], off);
        }
    }
    if (group == 0) {
        #pragma unroll
        for (int nf = 0; nf < 4; nf++) {
            #pragma unroll
            for (int e = 0; e < 2; e++) {
                int c = wc * 32 + nf * 8 + tig * 2 + e;
                scs[c][wr] = cs[nf * 2 + e];
                scq[c][wr] = cq[nf * 2 + e];
            }
        }
    }
    __syncthreads();
    if (tid < D_OUT) {
        g_psum[h][blockIdx.x][tid] = scs[tid][0] + scs[tid][1];
        g_psq[h][blockIdx.x][tid]  = scq[tid][0] + scq[tid][1];
    }
}

// ---------------- stage 1b: whitening stats finalize ----------------
__global__ void stats_final() {
    __shared__ double ssum[4][D_OUT];
    __shared__ double ssq[4][D_OUT];
    int set = blockIdx.x;
    int t = threadIdx.x & 127;
    int part = threadIdx.x >> 7;
    double s = 0.0, q = 0.0;
    for (int b = 0; b < 16; b++) {
        s += (double)g_psum[set][part * 16 + b][t];
        q += (double)g_psq[set][part * 16 + b][t];
    }
    ssum[part][t] = s; ssq[part][t] = q;
    __syncthreads();
    if (part == 0) {
        double S = ssum[0][t] + ssum[1][t] + ssum[2][t] + ssum[3][t];
        double Q = ssq[0][t] + ssq[1][t] + ssq[2][t] + ssq[3][t];
        double n = (double)BATCH;
        double mean = S / n;
        double var = (Q - S * S / n) / (n - 1.0);
        if (var < 0.0) var = 0.0;
        g_mean[set][t] = (float)mean;
        g_sd[set][t] = (float)(sqrt(var) + 1e-5);
    }
}

// ---------------- stage 1c: fused whiten + L2 normalize + pos dots + scaled bf16 ----------------
__global__ void norm_pos() {
    __shared__ float wss[4][3];
    __shared__ float wpp[4][3];
    int i = blockIdx.x;
    int t = threadIdx.x;
    int wid = t >> 5, lane = t & 31;

    float z[3], ssl[3];
    #pragma unroll
    for (int s = 0; s < 3; s++) {
        float v = (g_Y[s][i * D_OUT + t] - g_mean[s][t]) / g_sd[s][t];
        z[s] = v;
        ssl[s] = v * v;
    }
    #pragma unroll
    for (int s = 0; s < 3; s++)
        #pragma unroll
        for (int o = 16; o > 0; o >>= 1) ssl[s] += __shfl_xor_sync(0xFFFFFFFFu, ssl[s], o);
    if (lane == 0) { wss[wid][0] = ssl[0]; wss[wid][1] = ssl[1]; wss[wid][2] = ssl[2]; }
    __syncthreads();
    #pragma unroll
    for (int s = 0; s < 3; s++) {
        float tot = wss[0][s] + wss[1][s] + wss[2][s] + wss[3][s];
        float nrm = fmaxf(sqrtf(tot), 1e-12f);
        z[s] /= nrm;
    }
    float p[3] = { z[0] * z[1], z[0] * z[2], z[1] * z[2] };
    #pragma unroll
    for (int s = 0; s < 3; s++)
        #pragma unroll
        for (int o = 16; o > 0; o >>= 1) p[s] += __shfl_xor_sync(0xFFFFFFFFu, p[s], o);
    if (lane == 0) { wpp[wid][0] = p[0]; wpp[wid][1] = p[1]; wpp[wid][2] = p[2]; }
    __syncthreads();
    if (t == 0) {
        #pragma unroll
        for (int s = 0; s < 3; s++)
            g_pos[s][i] = wpp[0][s] + wpp[1][s] + wpp[2][s] + wpp[3][s];
    }
    #pragma unroll
    for (int s = 0; s < 3; s++)
        g_Zhi[s][i * D_OUT + t] = __float2bfloat16(z[s] * ZSCALE);
}

// ---------------- stage 2: hi-only bf16 gram, log2-domain, triangle symmetry ----------------
#define SOFF_A    0
#define SOFF_B(b) (TILE_BYTES + (b) * TILE_BYTES)
#define SOFF_RED  (3 * TILE_BYTES)
#define GRAM_SMEM (3 * TILE_BYTES + 2048)   // 106496

__global__ __launch_bounds__(256, 2) void gram_kernel() {
    extern __shared__ unsigned char smem[];
    uint32_t sb = smem_u32(smem);
    float* red = (float*)(smem + SOFF_RED);   // reused: [128][4] rowsum red, [128][2] col red

    const int tid = threadIdx.x, lane = tid & 31, w = tid >> 5;
    const int wr = w >> 2, wc = w & 3, group = lane >> 2, tig = lane & 3;

    const int g = blockIdx.z;
    const int it = blockIdx.x;
    const int chunk = blockIdx.y;
    const int same = c_same[g];

    // triangle: symmetric grams only process j-tiles >= it
    if (same && chunk * 16 + 15 < it) return;
    const int jtFirst = same ? max(it, chunk * 16) : chunk * 16;
    const int jtEndEx = chunk * 16 + 16;

    const __nv_bfloat16* __restrict__ A = g_Zhi[c_ga[g]];
    const __nv_bfloat16* __restrict__ B = g_Zhi[c_gb[g]];
    const int iBase = it * GTILE;

    load_tile(sb + SOFF_A, A + (size_t)iBase * D_OUT, D_OUT, tid);
    load_tile(sb + SOFF_B(0), B + (size_t)jtFirst * GTILE * D_OUT, D_OUT, tid);
    cp_commit();

    const uint32_t rowSel = (uint32_t)(lane & 15) * TPITCH;
    const uint32_t colSel = (uint32_t)((lane >> 4) << 4);
    const uint32_t aBase = sb + SOFF_A + (uint32_t)(wr * 64) * TPITCH + rowSel + colSel;
    const uint32_t bOff = (uint32_t)(wc * 32) * TPITCH + rowSel + colSel;

    float rsacc[8] = {0, 0, 0, 0, 0, 0, 0, 0};

    for (int jt = jtFirst; jt < jtEndEx; jt++) {
        const int buf = (jt - jtFirst) & 1;
        const int jBase = jt * GTILE;

        cp_wait0();
        __syncthreads();

        if (jt + 1 < jtEndEx) {
            load_tile(sb + SOFF_B(buf ^ 1), B + (size_t)(jBase + GTILE) * D_OUT, D_OUT, tid);
            cp_commit();
        }

        const uint32_t bBase = sb + SOFF_B(buf) + bOff;

        float acc[4][4][4];
        #pragma unroll
        for (int mf = 0; mf < 4; mf++)
            #pragma unroll
            for (int nf = 0; nf < 4; nf++)
                #pragma unroll
                for (int e = 0; e < 4; e++) acc[mf][nf][e] = 0.0f;

        mma_pass(acc, aBase, bBase);

        if (!same) {
            // cross gram: rowsums only
            #pragma unroll
            for (int mf = 0; mf < 4; mf++) {
                float s0 = 0.0f, s1 = 0.0f;
                #pragma unroll
                for (int nf = 0; nf < 4; nf++) {
                    if (mf == 0) {
                        s0 += tex2(acc[mf][nf][0]) + tex2(acc[mf][nf][1]);
                        s1 += tex2(acc[mf][nf][2]) + tex2(acc[mf][nf][3]);
                    } else {
                        s0 += ex2(acc[mf][nf][0]) + ex2(acc[mf][nf][1]);
                        s1 += ex2(acc[mf][nf][2]) + ex2(acc[mf][nf][3]);
                    }
                }
                rsacc[mf * 2 + 0] += s0;
                rsacc[mf * 2 + 1] += s1;
            }
        } else if (jBase == iBase) {
            // symmetric diagonal tile: rowsums with masked diag (counts rows once)
            #pragma unroll
            for (int mf = 0; mf < 4; mf++) {
                const int r0 = wr * 64 + mf * 16 + group;
                float s0 = 0.0f, s1 = 0.0f;
                #pragma unroll
                for (int nf = 0; nf < 4; nf++) {
                    const int c0 = wc * 32 + nf * 8 + tig * 2;
                    #pragma unroll
                    for (int e = 0; e < 4; e++) {
                        const int r = r0 + (e >> 1) * 8;
                        const int c = c0 + (e & 1);
                        float ev = (r == c) ? 1.0f : ex2(acc[mf][nf][e]);
                        if (e < 2) s0 += ev; else s1 += ev;
                    }
                }
                rsacc[mf * 2 + 0] += s0;
                rsacc[mf * 2 + 1] += s1;
            }
        } else {
            // symmetric off-diag tile (jt > it): rowsums for block it + colsums for block jt
            float colp[8] = {0, 0, 0, 0, 0, 0, 0, 0};
            #pragma unroll
            for (int mf = 0; mf < 4; mf++) {
                float s0 = 0.0f, s1 = 0.0f;
                #pragma unroll
                for (int nf = 0; nf < 4; nf++) {
                    float e0, e1, e2, e3;
                    if (mf == 0) {
                        e0 = tex2(acc[mf][nf][0]); e1 = tex2(acc[mf][nf][1]);
                        e2 = tex2(acc[mf][nf][2]); e3 = tex2(acc[mf][nf][3]);
                    } else {
                        e0 = ex2(acc[mf][nf][0]); e1 = ex2(acc[mf][nf][1]);
                        e2 = ex2(acc[mf][nf][2]); e3 = ex2(acc[mf][nf][3]);
                    }
                    s0 += e0 + e1;
                    s1 += e2 + e3;
                    colp[nf * 2 + 0] += e0 + e2;
                    colp[nf * 2 + 1] += e1 + e3;
                }
                rsacc[mf * 2 + 0] += s0;
                rsacc[mf * 2 + 1] += s1;
            }
            // reduce colp over the 8 row-groups in this warp
            #pragma unroll
            for (int s = 0; s < 8; s++) {
                #pragma unroll
                for (int off = 4; off <= 16; off <<= 1)
                    colp[s] += __shfl_xor_sync(0xFFFFFFFFu, colp[s], off);
            }
            if (group == 0) {
                #pragma unroll
                for (int nf = 0; nf < 4; nf++) {
                    #pragma unroll
                    for (int e = 0; e < 2; e++) {
                        int c = wc * 32 + nf * 8 + tig * 2 + e;
                        red[c * 2 + wr] = colp[nf * 2 + e];
                    }
                }
            }
            __syncthreads();
            if (tid < 128)
                g_colpart[g][it][jBase + tid] = red[tid * 2] + red[tid * 2 + 1];
            // next-iter top __syncthreads guards red reuse
        }
    }

    // rowsum partial: reduce across tig lanes, then across warp-cols via smem
    #pragma unroll
    for (int s = 0; s < 8; s++) {
        float v = rsacc[s];
        v += __shfl_xor_sync(0xFFFFFFFFu, v, 1);
        v += __shfl_xor_sync(0xFFFFFFFFu, v, 2);
        rsacc[s] = v;
    }
    __syncthreads();
    if (tig == 0) {
        #pragma unroll
        for (int mf = 0; mf < 4; mf++) {
            #pragma unroll
            for (int e = 0; e < 2; e++) {
                int r = wr * 64 + mf * 16 + group + e * 8;
                red[r * 4 + wc] = rsacc[mf * 2 + e];
            }
        }
    }
    __syncthreads();
    if (tid < 128) {
        float s = red[tid * 4 + 0] + red[tid * 4 + 1] + red[tid * 4 + 2] + red[tid * 4 + 3];
        g_rspart[g][chunk][iBase + tid] = s;
    }
}

// ---------------- stage 3: loss (two-stage, deterministic) ----------------
__global__ void loss_part() {
    __shared__ double sred[128];
    int t = threadIdx.x;
    int i = blockIdx.x * 128 + t;
    int blk = i >> 7;             // i-tile index of this row
    int cmin = blk >> 4;          // first valid row-chunk for symmetric grams

    // symmetric grams: row partials (chunks >= cmin) + col partials (it < blk)
    float rsBB = 0.0f, rsEE = 0.0f;
    for (int c = cmin; c < NCHUNK; c++) {
        rsBB += g_rspart[0][c][i];
        rsEE += g_rspart[1][c][i];
    }
    for (int it2 = 0; it2 < blk; it2++) {
        rsBB += g_colpart[0][it2][i];
        rsEE += g_colpart[1][it2][i];
    }
    // cross grams: all 4 chunk partials
    float rsBE = 0.0f, rsBF = 0.0f, rsEF = 0.0f;
    #pragma unroll
    for (int c = 0; c < NCHUNK; c++) {
        rsBE += g_rspart[2][c][i];
        rsBF += g_rspart[3][c][i];
        rsEF += g_rspart[4][c][i];
    }
    double acc = 0.0;
    acc += (double)logf(rsBB + rsBE) - (double)g_pos[0][i];
    acc += (double)logf(rsBB + rsBF) - (double)g_pos[1][i];
    acc += (double)logf(rsEE + rsEF) - (double)g_pos[2][i];
    sred[t] = acc;
    __syncthreads();
    for (int s = 64; s > 0; s >>= 1) {
        if (t < s) sred[t] += sred[t + s];
        __syncthreads();
    }
    if (t == 0) g_lpart[blockIdx.x] = sred[0];
}

__global__ void loss_final(float* __restrict__ out) {
    __shared__ double s[64];
    int t = threadIdx.x;
    s[t] = g_lpart[t];
    __syncthreads();
    for (int k = 32; k > 0; k >>= 1) {
        if (t < k) s[t] += s[t + k];
        __syncthreads();
    }
    if (t == 0) out[0] = (float)(s[0] / (3.0 * (double)BATCH));
}

// ---------------- launch ----------------
extern "C" void kernel_launch(void* const* d_in, const int* in_sizes, int n_in,
                              void* d_out, int out_size)
{
    static bool inited = false;
    if (!inited) {
        cudaFuncSetAttribute(gram_kernel, cudaFuncAttributeMaxDynamicSharedMemorySize, GRAM_SMEM);
        cudaFuncSetAttribute(mlp_gemmA, cudaFuncAttributeMaxDynamicSharedMemorySize, MLP_SMEM);
        cudaFuncSetAttribute(mlp_gemmB, cudaFuncAttributeMaxDynamicSharedMemorySize, MLP_SMEM);
        inited = true;
    }

    WArgs wa;
    BArgs ba;
    for (int m = 0; m < 3; m++) {
        wa.W1[m] = (const float*)d_in[3 + 4 * m];
        ba.b1[m] = (const float*)d_in[4 + 4 * m];
        wa.W2[m] = (const float*)d_in[5 + 4 * m];
        ba.b2[m] = (const float*)d_in[6 + 4 * m];
    }

    split_x<<<dim3(BATCH * D_IN / 1024, 3), 256>>>(
        (const float*)d_in[0], (const float*)d_in[1], (const float*)d_in[2]);
    split_w<<<dim3((D_IN * D_HID + D_HID * D_OUT) / 256, 3), 256>>>(wa);

    mlp_gemmA<<<dim3(BATCH / 128, 2, 3), 256, MLP_SMEM>>>(ba);
    mlp_gemmB<<<dim3(BATCH / 128, 1, 3), 256, MLP_SMEM>>>(ba);

    stats_final<<<3, 512>>>();
    norm_pos<<<BATCH, 128>>>();

    gram_kernel<<<dim3(BATCH / GTILE, NCHUNK, 5), 256, GRAM_SMEM>>>();

    loss_part<<<64, 128>>>();
    loss_final<<<1, 64>>>((float*)d_out);
}